// round 1
// baseline (speedup 1.0000x reference)
#include <cuda_runtime.h>
#include <math.h>

#define S_LEN 2048
#define HID_D 2048
#define NH 16
#define HD 128
#define DR 64
#define DQK 192
#define CKV 512
#define CQ 1536

// ---------------- scratch (static device allocations; no cudaMalloc) -------
__device__ float g_cKV[S_LEN * CKV];
__device__ float g_cQ [S_LEN * CQ];
__device__ float g_Qb [NH * S_LEN * DQK];   // [h][s][192]  (0:128 = q_C, 128:192 = rope(q_R))
__device__ float g_Kb [NH * S_LEN * DQK];   // [h][s][192]
__device__ float g_Vb [NH * S_LEN * HD];    // [h][s][128]
__device__ float g_qR [S_LEN * NH * DR];    // pre-rope q_R
__device__ float g_kR [S_LEN * DR];         // pre-rope k_R
__device__ float g_AO [S_LEN * NH * HD];    // attention output, [s][h*128+d]

// ---------------- generic tiled SGEMM: C = A[MxK] @ B[KxN] -----------------
// MODE 0: row-major C [M,N] (col<N guarded)
// MODE 1: head-split 192-stride: C[(col>>7)][row][col&127] over [h][S][192]
// MODE 2: head-split 128-stride: C[(col>>7)][row][col&127] over [h][S][128]
template <int MODE>
__global__ __launch_bounds__(256)
void sgemm_kernel(const float* __restrict__ A, const float* __restrict__ B,
                  float* __restrict__ C, int M, int N, int K)
{
    __shared__ float As[16][132];   // padded: conflict-free transpose store
    __shared__ float Bs[16][128];
    const int tid = threadIdx.x;
    const int m0 = blockIdx.y * 128;
    const int n0 = blockIdx.x * 128;
    const int tr = tid >> 4;        // 0..15
    const int tc = tid & 15;        // 0..15

    float acc[8][8];
#pragma unroll
    for (int i = 0; i < 8; i++)
#pragma unroll
        for (int j = 0; j < 8; j++) acc[i][j] = 0.f;

    for (int k0 = 0; k0 < K; k0 += 16) {
        // A tile 128x16 -> As[k][m] (transposed)
#pragma unroll
        for (int t = 0; t < 2; t++) {
            int idx = tid + t * 256;          // 0..511 float4s
            int r   = idx >> 2;               // 0..127
            int kc  = (idx & 3) * 4;          // 0,4,8,12
            float4 v = *(const float4*)&A[(size_t)(m0 + r) * K + k0 + kc];
            As[kc + 0][r] = v.x; As[kc + 1][r] = v.y;
            As[kc + 2][r] = v.z; As[kc + 3][r] = v.w;
        }
        // B tile 16x128 -> Bs[k][n]
#pragma unroll
        for (int t = 0; t < 2; t++) {
            int idx = tid + t * 256;
            int kk  = idx >> 5;               // 0..15
            int c4  = (idx & 31) * 4;         // 0..124
            float4 v;
            if (n0 + c4 < N)
                v = *(const float4*)&B[(size_t)(k0 + kk) * N + n0 + c4];
            else
                v = make_float4(0.f, 0.f, 0.f, 0.f);
            *(float4*)&Bs[kk][c4] = v;
        }
        __syncthreads();
#pragma unroll
        for (int kk = 0; kk < 16; kk++) {
            float4 a0 = *(const float4*)&As[kk][tr * 8];
            float4 a1 = *(const float4*)&As[kk][tr * 8 + 4];
            float4 b0 = *(const float4*)&Bs[kk][tc * 8];
            float4 b1 = *(const float4*)&Bs[kk][tc * 8 + 4];
            float ra[8] = {a0.x, a0.y, a0.z, a0.w, a1.x, a1.y, a1.z, a1.w};
            float rb[8] = {b0.x, b0.y, b0.z, b0.w, b1.x, b1.y, b1.z, b1.w};
#pragma unroll
            for (int i = 0; i < 8; i++)
#pragma unroll
                for (int j = 0; j < 8; j++) acc[i][j] += ra[i] * rb[j];
        }
        __syncthreads();
    }

#pragma unroll
    for (int i = 0; i < 8; i++) {
        int row = m0 + tr * 8 + i;
#pragma unroll
        for (int j = 0; j < 8; j++) {
            int col = n0 + tc * 8 + j;
            float v = acc[i][j];
            if (MODE == 0) {
                if (col < N) C[(size_t)row * N + col] = v;
            } else if (MODE == 1) {
                C[(size_t)((col >> 7) * S_LEN + row) * DQK + (col & 127)] = v;
            } else {
                C[(size_t)((col >> 7) * S_LEN + row) * HD + (col & 127)] = v;
            }
        }
    }
}

// ---------------- RoPE -----------------------------------------------------
// rope(x)[d]      = x[d]*cos - x[d+32]*sin   (d < 32)
// rope(x)[d+32]   = x[d+32]*cos + x[d]*sin
__global__ void rope_q_kernel()
{
    int idx = blockIdx.x * blockDim.x + threadIdx.x;
    if (idx >= S_LEN * NH * 32) return;
    int i = idx & 31;
    int h = (idx >> 5) & 15;
    int t = idx >> 9;
    float invf = powf(10000.0f, -(2.0f * i) / 64.0f);
    float ang = (float)t * invf;
    float s, c;
    sincosf(ang, &s, &c);
    const float* x = g_qR + (size_t)t * (NH * DR) + h * DR;
    float x1 = x[i], x2 = x[i + 32];
    float* out = g_Qb + (size_t)(h * S_LEN + t) * DQK + HD;
    out[i]      = x1 * c - x2 * s;
    out[i + 32] = x2 * c + x1 * s;
}

__global__ void rope_k_kernel()
{
    int idx = blockIdx.x * blockDim.x + threadIdx.x;
    if (idx >= S_LEN * 32) return;
    int i = idx & 31;
    int t = idx >> 5;
    float invf = powf(10000.0f, -(2.0f * i) / 64.0f);
    float ang = (float)t * invf;
    float s, c;
    sincosf(ang, &s, &c);
    const float* x = g_kR + (size_t)t * DR;
    float r1 = x[i] * c - x[i + 32] * s;
    float r2 = x[i + 32] * c + x[i] * s;
#pragma unroll
    for (int h = 0; h < NH; h++) {
        float* out = g_Kb + (size_t)(h * S_LEN + t) * DQK + HD;
        out[i] = r1;
        out[i + 32] = r2;
    }
}

// ---------------- causal flash attention (fp32, BM=BN=64, 256 thr) ---------
__global__ __launch_bounds__(256)
void attn_kernel()
{
    extern __shared__ float sm[];
    float* Qs = sm;                  // [16][64]
    float* Ks = Qs + 16 * 64;        // [16][64]
    float* Ps = Ks + 16 * 64;        // [64][65] (padded)
    float* Vs = Ps + 64 * 65;        // [64][128]

    const int h  = blockIdx.y;
    const int m0 = blockIdx.x * 64;
    const int tid = threadIdx.x;
    const int rg = tid >> 4;         // row group 0..15 (4 rows each)
    const int cg = tid & 15;         // col group 0..15
    const float scale = rsqrtf((float)DQK);
    const float* Q = g_Qb + (size_t)h * S_LEN * DQK;
    const float* K = g_Kb + (size_t)h * S_LEN * DQK;
    const float* V = g_Vb + (size_t)h * S_LEN * HD;

    float o[4][8];
    float mi[4], li[4];
#pragma unroll
    for (int i = 0; i < 4; i++) {
        mi[i] = -INFINITY; li[i] = 0.f;
#pragma unroll
        for (int c = 0; c < 8; c++) o[i][c] = 0.f;
    }

    const int lr = tid >> 2;         // 0..63 (load row)
    const int lc = (tid & 3) * 4;    // 0,4,8,12 (load col4)

    for (int n0 = 0; n0 <= m0; n0 += 64) {
        float sc[4][4];
#pragma unroll
        for (int i = 0; i < 4; i++)
#pragma unroll
            for (int j = 0; j < 4; j++) sc[i][j] = 0.f;

        // S = Q K^T over d=192 in 16-chunks
        for (int d0 = 0; d0 < DQK; d0 += 16) {
            float4 qv = *(const float4*)&Q[(size_t)(m0 + lr) * DQK + d0 + lc];
            float4 kv = *(const float4*)&K[(size_t)(n0 + lr) * DQK + d0 + lc];
            Qs[(lc + 0) * 64 + lr] = qv.x; Qs[(lc + 1) * 64 + lr] = qv.y;
            Qs[(lc + 2) * 64 + lr] = qv.z; Qs[(lc + 3) * 64 + lr] = qv.w;
            Ks[(lc + 0) * 64 + lr] = kv.x; Ks[(lc + 1) * 64 + lr] = kv.y;
            Ks[(lc + 2) * 64 + lr] = kv.z; Ks[(lc + 3) * 64 + lr] = kv.w;
            __syncthreads();
#pragma unroll
            for (int kk = 0; kk < 16; kk++) {
                float4 qf = *(const float4*)&Qs[kk * 64 + rg * 4];
                float4 kf = *(const float4*)&Ks[kk * 64 + cg * 4];
                float ra[4] = {qf.x, qf.y, qf.z, qf.w};
                float rb[4] = {kf.x, kf.y, kf.z, kf.w};
#pragma unroll
                for (int i = 0; i < 4; i++)
#pragma unroll
                    for (int j = 0; j < 4; j++) sc[i][j] += ra[i] * rb[j];
            }
            __syncthreads();
        }

        // scale + causal mask (only diagonal tile needs it)
        const bool diag = (n0 == m0);
#pragma unroll
        for (int i = 0; i < 4; i++)
#pragma unroll
            for (int j = 0; j < 4; j++) {
                float v = sc[i][j] * scale;
                if (diag && (cg * 4 + j > rg * 4 + i)) v = -1e30f;
                sc[i][j] = v;
            }

        // online softmax (row reduce across 16 lanes sharing rows)
#pragma unroll
        for (int i = 0; i < 4; i++) {
            float rm = fmaxf(fmaxf(sc[i][0], sc[i][1]), fmaxf(sc[i][2], sc[i][3]));
#pragma unroll
            for (int off = 8; off > 0; off >>= 1)
                rm = fmaxf(rm, __shfl_xor_sync(0xffffffffu, rm, off));
            float mnew = fmaxf(mi[i], rm);
            float al = expf(mi[i] - mnew);
            float rs = 0.f;
#pragma unroll
            for (int j = 0; j < 4; j++) {
                float p = expf(sc[i][j] - mnew);
                sc[i][j] = p;
                rs += p;
            }
#pragma unroll
            for (int off = 8; off > 0; off >>= 1)
                rs += __shfl_xor_sync(0xffffffffu, rs, off);
            li[i] = li[i] * al + rs;
            mi[i] = mnew;
#pragma unroll
            for (int c = 0; c < 8; c++) o[i][c] *= al;
        }

        // stash P, stage V
#pragma unroll
        for (int i = 0; i < 4; i++)
#pragma unroll
            for (int j = 0; j < 4; j++)
                Ps[(rg * 4 + i) * 65 + cg * 4 + j] = sc[i][j];
#pragma unroll
        for (int t = 0; t < 8; t++) {
            int idx = tid + t * 256;          // 0..2047 float4s
            int r  = idx >> 5;
            int c4 = (idx & 31) * 4;
            *(float4*)&Vs[r * 128 + c4] =
                *(const float4*)&V[(size_t)(n0 + r) * HD + c4];
        }
        __syncthreads();

        // O += P V
#pragma unroll 2
        for (int j = 0; j < 64; j++) {
            float p[4];
            p[0] = Ps[(rg * 4 + 0) * 65 + j];
            p[1] = Ps[(rg * 4 + 1) * 65 + j];
            p[2] = Ps[(rg * 4 + 2) * 65 + j];
            p[3] = Ps[(rg * 4 + 3) * 65 + j];
            float4 va = *(const float4*)&Vs[j * 128 + cg * 8];
            float4 vb = *(const float4*)&Vs[j * 128 + cg * 8 + 4];
            float v8[8] = {va.x, va.y, va.z, va.w, vb.x, vb.y, vb.z, vb.w};
#pragma unroll
            for (int i = 0; i < 4; i++)
#pragma unroll
                for (int c = 0; c < 8; c++) o[i][c] += p[i] * v8[c];
        }
        __syncthreads();
    }

    // finalize: O / l, write [s][h*128+d]
#pragma unroll
    for (int i = 0; i < 4; i++) {
        float inv = 1.f / li[i];
        int row = m0 + rg * 4 + i;
        float* outp = g_AO + (size_t)row * (NH * HD) + h * HD + cg * 8;
#pragma unroll
        for (int c = 0; c < 8; c++) outp[c] = o[i][c] * inv;
    }
}

// ---------------- launch ----------------------------------------------------
extern "C" void kernel_launch(void* const* d_in, const int* in_sizes, int n_in,
                              void* d_out, int out_size)
{
    const float* X     = (const float*)d_in[0];
    // d_in[1] = mask (causal; implemented directly)
    const float* W_DKV = (const float*)d_in[2];
    const float* W_UK  = (const float*)d_in[3];
    const float* W_UV  = (const float*)d_in[4];
    const float* W_DQ  = (const float*)d_in[5];
    const float* W_UQ  = (const float*)d_in[6];
    const float* W_QR  = (const float*)d_in[7];
    const float* W_KR  = (const float*)d_in[8];
    const float* W_O   = (const float*)d_in[9];
    float* out = (float*)d_out;

    float *cKV, *cQ, *Qb, *Kb, *Vb, *qR, *kR, *AO;
    cudaGetSymbolAddress((void**)&cKV, g_cKV);
    cudaGetSymbolAddress((void**)&cQ,  g_cQ);
    cudaGetSymbolAddress((void**)&Qb,  g_Qb);
    cudaGetSymbolAddress((void**)&Kb,  g_Kb);
    cudaGetSymbolAddress((void**)&Vb,  g_Vb);
    cudaGetSymbolAddress((void**)&qR,  g_qR);
    cudaGetSymbolAddress((void**)&kR,  g_kR);
    cudaGetSymbolAddress((void**)&AO,  g_AO);

    dim3 blk(256);
    // c_KV = X @ W_DKV
    sgemm_kernel<0><<<dim3(CKV / 128, S_LEN / 128), blk>>>(X, W_DKV, cKV, S_LEN, CKV, HID_D);
    // k_C -> K_buf[h][s][0:128]
    sgemm_kernel<1><<<dim3(16, 16), blk>>>(cKV, W_UK, Kb, S_LEN, NH * HD, CKV);
    // v -> V_buf[h][s][:]
    sgemm_kernel<2><<<dim3(16, 16), blk>>>(cKV, W_UV, Vb, S_LEN, NH * HD, CKV);
    // c_Q = X @ W_DQ
    sgemm_kernel<0><<<dim3(CQ / 128, 16), blk>>>(X, W_DQ, cQ, S_LEN, CQ, HID_D);
    // q_C -> Q_buf[h][s][0:128]
    sgemm_kernel<1><<<dim3(16, 16), blk>>>(cQ, W_UQ, Qb, S_LEN, NH * HD, CQ);
    // q_R (pre-rope)
    sgemm_kernel<0><<<dim3(NH * DR / 128, 16), blk>>>(cQ, W_QR, qR, S_LEN, NH * DR, CQ);
    // k_R (pre-rope), N=64 partial tile
    sgemm_kernel<0><<<dim3(1, 16), blk>>>(X, W_KR, kR, S_LEN, DR, HID_D);
    // rope into Q_buf / K_buf [128:192]
    rope_q_kernel<<<(S_LEN * NH * 32) / 256, 256>>>();
    rope_k_kernel<<<(S_LEN * 32) / 256, 256>>>();
    // causal flash attention
    cudaFuncSetAttribute(attn_kernel, cudaFuncAttributeMaxDynamicSharedMemorySize, 57600);
    attn_kernel<<<dim3(S_LEN / 64, NH), 256, 57600>>>();
    // out = AO @ W_O
    sgemm_kernel<0><<<dim3(16, 16), blk>>>(AO, W_O, out, S_LEN, HID_D, NH * HD);
}

// round 2
// speedup vs baseline: 1.6467x; 1.6467x over previous
#include <cuda_runtime.h>
#include <math.h>

#define S_LEN 2048
#define HID_D 2048
#define NH 16
#define HD 128
#define DR 64
#define DQK 192
#define CKV 512
#define CQ 1536

// ---------------- scratch (static device allocations; no cudaMalloc) -------
__device__ float g_cKV[S_LEN * CKV];
__device__ float g_cQ [S_LEN * CQ];
__device__ float g_Qb [NH * S_LEN * DQK];   // [h][s][192]  (0:128 = q_C, 128:192 = rope(q_R))
__device__ float g_Kb [NH * S_LEN * DQK];   // [h][s][192]
__device__ float g_Vb [NH * S_LEN * HD];    // [h][s][128]
__device__ float g_qR [S_LEN * NH * DR];    // pre-rope q_R
__device__ float g_kR [S_LEN * DR];         // pre-rope k_R
__device__ float g_AO [S_LEN * NH * HD];    // attention output, [s][h*128+d]

// ---------------- tf32 helpers ---------------------------------------------
__device__ __forceinline__ unsigned f2tf(float x) {
    unsigned u;
    asm("cvt.rna.tf32.f32 %0, %1;" : "=r"(u) : "f"(x));
    return u;
}

__device__ __forceinline__ void mma8(float c[4], const unsigned a[4], const unsigned b[2]) {
    asm volatile(
        "mma.sync.aligned.m16n8k8.row.col.f32.tf32.tf32.f32 "
        "{%0,%1,%2,%3}, {%4,%5,%6,%7}, {%8,%9}, {%0,%1,%2,%3};\n"
        : "+f"(c[0]), "+f"(c[1]), "+f"(c[2]), "+f"(c[3])
        : "r"(a[0]), "r"(a[1]), "r"(a[2]), "r"(a[3]), "r"(b[0]), "r"(b[1]));
}

// ---------------- tf32 tensor-core GEMM: C = A[MxK] @ B[KxN] ---------------
// 128x128 block tile, BK=16, 8 warps each 64x32. Double-buffered smem.
// MODE 0: row-major C [M,N] (col<N guarded)
// MODE 1: head-split 192-stride: C[(col>>7)][row][col&127] over [h][S][192]
// MODE 2: head-split 128-stride: C[(col>>7)][row][col&127] over [h][S][128]
template <int MODE>
__global__ __launch_bounds__(256)
void mma_gemm(const float* __restrict__ A, const float* __restrict__ B,
              float* __restrict__ C, int M, int N, int K)
{
    __shared__ unsigned As[2][128][20];   // row-major, stride 20: frag LDS conflict-free
    __shared__ unsigned Bs[2][16][136];   // row-major, stride 136: frag LDS conflict-free
    const int tid  = threadIdx.x;
    const int lane = tid & 31;
    const int warp = tid >> 5;
    const int wm   = warp & 1;            // 0..1
    const int wn   = warp >> 1;           // 0..3
    const int m0   = blockIdx.y * 128;
    const int n0   = blockIdx.x * 128;
    const int fr   = lane >> 2;           // 0..7
    const int fc   = lane & 3;            // 0..3

    float acc[4][4][4];
#pragma unroll
    for (int mt = 0; mt < 4; mt++)
#pragma unroll
        for (int nt = 0; nt < 4; nt++)
#pragma unroll
            for (int i = 0; i < 4; i++) acc[mt][nt][i] = 0.f;

    float4 ra[2], rb[2];

    // per-thread load coords
    const int rowA0 = (tid + 0)   >> 2;   const int kcA0 = ((tid + 0)   & 3) * 4;
    const int rowA1 = (tid + 256) >> 2;   const int kcA1 = ((tid + 256) & 3) * 4;
    const int kkB0  = (tid + 0)   >> 5;   const int c4B0 = ((tid + 0)   & 31) * 4;
    const int kkB1  = (tid + 256) >> 5;   const int c4B1 = ((tid + 256) & 31) * 4;

#define LDG_TILE(k0)                                                            \
    {                                                                           \
        ra[0] = *(const float4*)&A[(size_t)(m0 + rowA0) * K + (k0) + kcA0];     \
        ra[1] = *(const float4*)&A[(size_t)(m0 + rowA1) * K + (k0) + kcA1];     \
        if (n0 + c4B0 < N)                                                      \
            rb[0] = *(const float4*)&B[(size_t)((k0) + kkB0) * N + n0 + c4B0];  \
        else rb[0] = make_float4(0.f, 0.f, 0.f, 0.f);                           \
        if (n0 + c4B1 < N)                                                      \
            rb[1] = *(const float4*)&B[(size_t)((k0) + kkB1) * N + n0 + c4B1];  \
        else rb[1] = make_float4(0.f, 0.f, 0.f, 0.f);                           \
    }

#define STS_TILE(buf)                                                           \
    {                                                                           \
        uint4 ua0 = make_uint4(f2tf(ra[0].x), f2tf(ra[0].y), f2tf(ra[0].z), f2tf(ra[0].w)); \
        uint4 ua1 = make_uint4(f2tf(ra[1].x), f2tf(ra[1].y), f2tf(ra[1].z), f2tf(ra[1].w)); \
        *(uint4*)&As[buf][rowA0][kcA0] = ua0;                                   \
        *(uint4*)&As[buf][rowA1][kcA1] = ua1;                                   \
        uint4 ub0 = make_uint4(f2tf(rb[0].x), f2tf(rb[0].y), f2tf(rb[0].z), f2tf(rb[0].w)); \
        uint4 ub1 = make_uint4(f2tf(rb[1].x), f2tf(rb[1].y), f2tf(rb[1].z), f2tf(rb[1].w)); \
        *(uint4*)&Bs[buf][kkB0][c4B0] = ub0;                                    \
        *(uint4*)&Bs[buf][kkB1][c4B1] = ub1;                                    \
    }

#define COMPUTE(buf)                                                            \
    {                                                                           \
        _Pragma("unroll")                                                       \
        for (int ks = 0; ks < 2; ks++) {                                        \
            unsigned af[4][4], bf[4][2];                                        \
            _Pragma("unroll")                                                   \
            for (int mt = 0; mt < 4; mt++) {                                    \
                int mr = wm * 64 + mt * 16 + fr;                                \
                af[mt][0] = As[buf][mr    ][ks * 8 + fc];                       \
                af[mt][1] = As[buf][mr + 8][ks * 8 + fc];                       \
                af[mt][2] = As[buf][mr    ][ks * 8 + fc + 4];                   \
                af[mt][3] = As[buf][mr + 8][ks * 8 + fc + 4];                   \
            }                                                                   \
            _Pragma("unroll")                                                   \
            for (int nt = 0; nt < 4; nt++) {                                    \
                int nc = wn * 32 + nt * 8 + fr;                                 \
                bf[nt][0] = Bs[buf][ks * 8 + fc    ][nc];                       \
                bf[nt][1] = Bs[buf][ks * 8 + fc + 4][nc];                       \
            }                                                                   \
            _Pragma("unroll")                                                   \
            for (int mt = 0; mt < 4; mt++)                                      \
                _Pragma("unroll")                                               \
                for (int nt = 0; nt < 4; nt++)                                  \
                    mma8(acc[mt][nt], af[mt], bf[nt]);                          \
        }                                                                       \
    }

    LDG_TILE(0);
    STS_TILE(0);
    __syncthreads();

    int buf = 0;
#pragma unroll 1
    for (int k0 = 16; k0 < K; k0 += 16) {
        LDG_TILE(k0);
        COMPUTE(buf);
        STS_TILE(buf ^ 1);
        __syncthreads();
        buf ^= 1;
    }
    COMPUTE(buf);

    // epilogue
#pragma unroll
    for (int mt = 0; mt < 4; mt++) {
#pragma unroll
        for (int nt = 0; nt < 4; nt++) {
            int row = m0 + wm * 64 + mt * 16 + fr;
            int col = n0 + wn * 32 + nt * 8 + fc * 2;
            float2 v0 = make_float2(acc[mt][nt][0], acc[mt][nt][1]);
            float2 v1 = make_float2(acc[mt][nt][2], acc[mt][nt][3]);
            if (MODE == 0) {
                if (col < N) {
                    *(float2*)&C[(size_t)row * N + col]       = v0;
                    *(float2*)&C[(size_t)(row + 8) * N + col] = v1;
                }
            } else if (MODE == 1) {
                int h = col >> 7, d = col & 127;
                *(float2*)&C[(size_t)((h * S_LEN) + row)     * DQK + d] = v0;
                *(float2*)&C[(size_t)((h * S_LEN) + row + 8) * DQK + d] = v1;
            } else {
                int h = col >> 7, d = col & 127;
                *(float2*)&C[(size_t)((h * S_LEN) + row)     * HD + d] = v0;
                *(float2*)&C[(size_t)((h * S_LEN) + row + 8) * HD + d] = v1;
            }
        }
    }
#undef LDG_TILE
#undef STS_TILE
#undef COMPUTE
}

// ---------------- RoPE -----------------------------------------------------
__global__ void rope_q_kernel()
{
    int idx = blockIdx.x * blockDim.x + threadIdx.x;
    if (idx >= S_LEN * NH * 32) return;
    int i = idx & 31;
    int h = (idx >> 5) & 15;
    int t = idx >> 9;
    float invf = powf(10000.0f, -(2.0f * i) / 64.0f);
    float ang = (float)t * invf;
    float s, c;
    sincosf(ang, &s, &c);
    const float* x = g_qR + (size_t)t * (NH * DR) + h * DR;
    float x1 = x[i], x2 = x[i + 32];
    float* out = g_Qb + (size_t)(h * S_LEN + t) * DQK + HD;
    out[i]      = x1 * c - x2 * s;
    out[i + 32] = x2 * c + x1 * s;
}

__global__ void rope_k_kernel()
{
    int idx = blockIdx.x * blockDim.x + threadIdx.x;
    if (idx >= S_LEN * 32) return;
    int i = idx & 31;
    int t = idx >> 5;
    float invf = powf(10000.0f, -(2.0f * i) / 64.0f);
    float ang = (float)t * invf;
    float s, c;
    sincosf(ang, &s, &c);
    const float* x = g_kR + (size_t)t * DR;
    float r1 = x[i] * c - x[i + 32] * s;
    float r2 = x[i + 32] * c + x[i] * s;
#pragma unroll
    for (int h = 0; h < NH; h++) {
        float* out = g_Kb + (size_t)(h * S_LEN + t) * DQK + HD;
        out[i] = r1;
        out[i + 32] = r2;
    }
}

// ---------------- causal flash attention (fp32, BM=BN=64, 256 thr) ---------
__global__ __launch_bounds__(256)
void attn_kernel()
{
    extern __shared__ float sm[];
    float* Qs = sm;                  // [16][64]
    float* Ks = Qs + 16 * 64;        // [16][64]
    float* Ps = Ks + 16 * 64;        // [64][65] (padded)
    float* Vs = Ps + 64 * 65;        // [64][128]

    const int h  = blockIdx.y;
    const int m0 = blockIdx.x * 64;
    const int tid = threadIdx.x;
    const int rg = tid >> 4;
    const int cg = tid & 15;
    const float scale = rsqrtf((float)DQK);
    const float* Q = g_Qb + (size_t)h * S_LEN * DQK;
    const float* K = g_Kb + (size_t)h * S_LEN * DQK;
    const float* V = g_Vb + (size_t)h * S_LEN * HD;

    float o[4][8];
    float mi[4], li[4];
#pragma unroll
    for (int i = 0; i < 4; i++) {
        mi[i] = -INFINITY; li[i] = 0.f;
#pragma unroll
        for (int c = 0; c < 8; c++) o[i][c] = 0.f;
    }

    const int lr = tid >> 2;
    const int lc = (tid & 3) * 4;

    for (int n0 = 0; n0 <= m0; n0 += 64) {
        float sc[4][4];
#pragma unroll
        for (int i = 0; i < 4; i++)
#pragma unroll
            for (int j = 0; j < 4; j++) sc[i][j] = 0.f;

        for (int d0 = 0; d0 < DQK; d0 += 16) {
            float4 qv = *(const float4*)&Q[(size_t)(m0 + lr) * DQK + d0 + lc];
            float4 kv = *(const float4*)&K[(size_t)(n0 + lr) * DQK + d0 + lc];
            Qs[(lc + 0) * 64 + lr] = qv.x; Qs[(lc + 1) * 64 + lr] = qv.y;
            Qs[(lc + 2) * 64 + lr] = qv.z; Qs[(lc + 3) * 64 + lr] = qv.w;
            Ks[(lc + 0) * 64 + lr] = kv.x; Ks[(lc + 1) * 64 + lr] = kv.y;
            Ks[(lc + 2) * 64 + lr] = kv.z; Ks[(lc + 3) * 64 + lr] = kv.w;
            __syncthreads();
#pragma unroll
            for (int kk = 0; kk < 16; kk++) {
                float4 qf = *(const float4*)&Qs[kk * 64 + rg * 4];
                float4 kf = *(const float4*)&Ks[kk * 64 + cg * 4];
                float raa[4] = {qf.x, qf.y, qf.z, qf.w};
                float rbb[4] = {kf.x, kf.y, kf.z, kf.w};
#pragma unroll
                for (int i = 0; i < 4; i++)
#pragma unroll
                    for (int j = 0; j < 4; j++) sc[i][j] += raa[i] * rbb[j];
            }
            __syncthreads();
        }

        const bool diag = (n0 == m0);
#pragma unroll
        for (int i = 0; i < 4; i++)
#pragma unroll
            for (int j = 0; j < 4; j++) {
                float v = sc[i][j] * scale;
                if (diag && (cg * 4 + j > rg * 4 + i)) v = -1e30f;
                sc[i][j] = v;
            }

#pragma unroll
        for (int i = 0; i < 4; i++) {
            float rm = fmaxf(fmaxf(sc[i][0], sc[i][1]), fmaxf(sc[i][2], sc[i][3]));
#pragma unroll
            for (int off = 8; off > 0; off >>= 1)
                rm = fmaxf(rm, __shfl_xor_sync(0xffffffffu, rm, off));
            float mnew = fmaxf(mi[i], rm);
            float al = expf(mi[i] - mnew);
            float rs = 0.f;
#pragma unroll
            for (int j = 0; j < 4; j++) {
                float p = expf(sc[i][j] - mnew);
                sc[i][j] = p;
                rs += p;
            }
#pragma unroll
            for (int off = 8; off > 0; off >>= 1)
                rs += __shfl_xor_sync(0xffffffffu, rs, off);
            li[i] = li[i] * al + rs;
            mi[i] = mnew;
#pragma unroll
            for (int c = 0; c < 8; c++) o[i][c] *= al;
        }

#pragma unroll
        for (int i = 0; i < 4; i++)
#pragma unroll
            for (int j = 0; j < 4; j++)
                Ps[(rg * 4 + i) * 65 + cg * 4 + j] = sc[i][j];
#pragma unroll
        for (int t = 0; t < 8; t++) {
            int idx = tid + t * 256;
            int r  = idx >> 5;
            int c4 = (idx & 31) * 4;
            *(float4*)&Vs[r * 128 + c4] =
                *(const float4*)&V[(size_t)(n0 + r) * HD + c4];
        }
        __syncthreads();

#pragma unroll 2
        for (int j = 0; j < 64; j++) {
            float p[4];
            p[0] = Ps[(rg * 4 + 0) * 65 + j];
            p[1] = Ps[(rg * 4 + 1) * 65 + j];
            p[2] = Ps[(rg * 4 + 2) * 65 + j];
            p[3] = Ps[(rg * 4 + 3) * 65 + j];
            float4 va = *(const float4*)&Vs[j * 128 + cg * 8];
            float4 vb = *(const float4*)&Vs[j * 128 + cg * 8 + 4];
            float v8[8] = {va.x, va.y, va.z, va.w, vb.x, vb.y, vb.z, vb.w};
#pragma unroll
            for (int i = 0; i < 4; i++)
#pragma unroll
                for (int c = 0; c < 8; c++) o[i][c] += p[i] * v8[c];
        }
        __syncthreads();
    }

#pragma unroll
    for (int i = 0; i < 4; i++) {
        float inv = 1.f / li[i];
        int row = m0 + rg * 4 + i;
        float* outp = g_AO + (size_t)row * (NH * HD) + h * HD + cg * 8;
#pragma unroll
        for (int c = 0; c < 8; c++) outp[c] = o[i][c] * inv;
    }
}

// ---------------- launch ----------------------------------------------------
extern "C" void kernel_launch(void* const* d_in, const int* in_sizes, int n_in,
                              void* d_out, int out_size)
{
    const float* X     = (const float*)d_in[0];
    const float* W_DKV = (const float*)d_in[2];
    const float* W_UK  = (const float*)d_in[3];
    const float* W_UV  = (const float*)d_in[4];
    const float* W_DQ  = (const float*)d_in[5];
    const float* W_UQ  = (const float*)d_in[6];
    const float* W_QR  = (const float*)d_in[7];
    const float* W_KR  = (const float*)d_in[8];
    const float* W_O   = (const float*)d_in[9];
    float* out = (float*)d_out;

    float *cKV, *cQ, *Qb, *Kb, *Vb, *qR, *kR, *AO;
    cudaGetSymbolAddress((void**)&cKV, g_cKV);
    cudaGetSymbolAddress((void**)&cQ,  g_cQ);
    cudaGetSymbolAddress((void**)&Qb,  g_Qb);
    cudaGetSymbolAddress((void**)&Kb,  g_Kb);
    cudaGetSymbolAddress((void**)&Vb,  g_Vb);
    cudaGetSymbolAddress((void**)&qR,  g_qR);
    cudaGetSymbolAddress((void**)&kR,  g_kR);
    cudaGetSymbolAddress((void**)&AO,  g_AO);

    dim3 blk(256);
    // c_KV = X @ W_DKV
    mma_gemm<0><<<dim3(CKV / 128, S_LEN / 128), blk>>>(X, W_DKV, cKV, S_LEN, CKV, HID_D);
    // k_C -> K_buf[h][s][0:128]
    mma_gemm<1><<<dim3(16, 16), blk>>>(cKV, W_UK, Kb, S_LEN, NH * HD, CKV);
    // v -> V_buf[h][s][:]
    mma_gemm<2><<<dim3(16, 16), blk>>>(cKV, W_UV, Vb, S_LEN, NH * HD, CKV);
    // c_Q = X @ W_DQ
    mma_gemm<0><<<dim3(CQ / 128, 16), blk>>>(X, W_DQ, cQ, S_LEN, CQ, HID_D);
    // q_C -> Q_buf[h][s][0:128]
    mma_gemm<1><<<dim3(16, 16), blk>>>(cQ, W_UQ, Qb, S_LEN, NH * HD, CQ);
    // q_R (pre-rope)
    mma_gemm<0><<<dim3(NH * DR / 128, 16), blk>>>(cQ, W_QR, qR, S_LEN, NH * DR, CQ);
    // k_R (pre-rope), N=64 partial tile
    mma_gemm<0><<<dim3(1, 16), blk>>>(X, W_KR, kR, S_LEN, DR, HID_D);
    // rope
    rope_q_kernel<<<(S_LEN * NH * 32) / 256, 256>>>();
    rope_k_kernel<<<(S_LEN * 32) / 256, 256>>>();
    // causal flash attention
    cudaFuncSetAttribute(attn_kernel, cudaFuncAttributeMaxDynamicSharedMemorySize, 57600);
    attn_kernel<<<dim3(S_LEN / 64, NH), 256, 57600>>>();
    // out = AO @ W_O
    mma_gemm<0><<<dim3(16, 16), blk>>>(AO, W_O, out, S_LEN, HID_D, NH * HD);
}

// round 3
// speedup vs baseline: 3.1498x; 1.9128x over previous
#include <cuda_runtime.h>
#include <cuda_bf16.h>
#include <math.h>

#define S_LEN 2048
#define HID_D 2048
#define NH 16
#define HD 128
#define DR 64
#define DQK 192
#define CKV 512
#define CQ 1536

// ---------------- scratch (static device allocations; no cudaMalloc) -------
__device__ float g_cKV[S_LEN * CKV];
__device__ float g_cQ [S_LEN * CQ];
__device__ float g_Qb [NH * S_LEN * DQK];   // [h][s][192]
__device__ float g_Kb [NH * S_LEN * DQK];   // [h][s][192]
__device__ float g_Vb [NH * S_LEN * HD];    // [h][s][128]
__device__ float g_qR [S_LEN * NH * DR];
__device__ float g_kR [S_LEN * DR];
__device__ float g_AO [S_LEN * NH * HD];    // [s][h*128+d]

// ---------------- tf32 helpers (projections, unchanged) ---------------------
__device__ __forceinline__ unsigned f2tf(float x) {
    unsigned u;
    asm("cvt.rna.tf32.f32 %0, %1;" : "=r"(u) : "f"(x));
    return u;
}

__device__ __forceinline__ void mma8(float c[4], const unsigned a[4], const unsigned b[2]) {
    asm volatile(
        "mma.sync.aligned.m16n8k8.row.col.f32.tf32.tf32.f32 "
        "{%0,%1,%2,%3}, {%4,%5,%6,%7}, {%8,%9}, {%0,%1,%2,%3};\n"
        : "+f"(c[0]), "+f"(c[1]), "+f"(c[2]), "+f"(c[3])
        : "r"(a[0]), "r"(a[1]), "r"(a[2]), "r"(a[3]), "r"(b[0]), "r"(b[1]));
}

// ---------------- bf16 helpers (attention) ----------------------------------
__device__ __forceinline__ void mma16(float c[4], const unsigned a[4], const unsigned b[2]) {
    asm volatile(
        "mma.sync.aligned.m16n8k16.row.col.f32.bf16.bf16.f32 "
        "{%0,%1,%2,%3}, {%4,%5,%6,%7}, {%8,%9}, {%0,%1,%2,%3};\n"
        : "+f"(c[0]), "+f"(c[1]), "+f"(c[2]), "+f"(c[3])
        : "r"(a[0]), "r"(a[1]), "r"(a[2]), "r"(a[3]), "r"(b[0]), "r"(b[1]));
}

__device__ __forceinline__ void split2(float x, unsigned short &hh, unsigned short &ll) {
    __nv_bfloat16 bh = __float2bfloat16(x);
    float hf = __bfloat162float(bh);
    __nv_bfloat16 bl = __float2bfloat16(x - hf);
    hh = __bfloat16_as_ushort(bh);
    ll = __bfloat16_as_ushort(bl);
}

__device__ __forceinline__ unsigned bfbits(float x) {
    return (unsigned)__bfloat16_as_ushort(__float2bfloat16(x));
}
__device__ __forceinline__ float bfval(float x) {
    return __bfloat162float(__float2bfloat16(x));
}
// pack (x,y) as bf16x2 hi-parts; lo-parts (residuals) in `lo`
__device__ __forceinline__ unsigned packsplit(float x, float y, unsigned &lo) {
    float xh = bfval(x), yh = bfval(y);
    unsigned hi = bfbits(x) | (bfbits(y) << 16);
    lo = bfbits(x - xh) | (bfbits(y - yh) << 16);
    return hi;
}

// ---------------- tf32 tensor-core GEMM (unchanged from round 2) ------------
template <int MODE>
__global__ __launch_bounds__(256)
void mma_gemm(const float* __restrict__ A, const float* __restrict__ B,
              float* __restrict__ C, int M, int N, int K)
{
    __shared__ unsigned As[2][128][20];
    __shared__ unsigned Bs[2][16][136];
    const int tid  = threadIdx.x;
    const int lane = tid & 31;
    const int warp = tid >> 5;
    const int wm   = warp & 1;
    const int wn   = warp >> 1;
    const int m0   = blockIdx.y * 128;
    const int n0   = blockIdx.x * 128;
    const int fr   = lane >> 2;
    const int fc   = lane & 3;

    float acc[4][4][4];
#pragma unroll
    for (int mt = 0; mt < 4; mt++)
#pragma unroll
        for (int nt = 0; nt < 4; nt++)
#pragma unroll
            for (int i = 0; i < 4; i++) acc[mt][nt][i] = 0.f;

    float4 ra[2], rb[2];

    const int rowA0 = (tid + 0)   >> 2;   const int kcA0 = ((tid + 0)   & 3) * 4;
    const int rowA1 = (tid + 256) >> 2;   const int kcA1 = ((tid + 256) & 3) * 4;
    const int kkB0  = (tid + 0)   >> 5;   const int c4B0 = ((tid + 0)   & 31) * 4;
    const int kkB1  = (tid + 256) >> 5;   const int c4B1 = ((tid + 256) & 31) * 4;

#define LDG_TILE(k0)                                                            \
    {                                                                           \
        ra[0] = *(const float4*)&A[(size_t)(m0 + rowA0) * K + (k0) + kcA0];     \
        ra[1] = *(const float4*)&A[(size_t)(m0 + rowA1) * K + (k0) + kcA1];     \
        if (n0 + c4B0 < N)                                                      \
            rb[0] = *(const float4*)&B[(size_t)((k0) + kkB0) * N + n0 + c4B0];  \
        else rb[0] = make_float4(0.f, 0.f, 0.f, 0.f);                           \
        if (n0 + c4B1 < N)                                                      \
            rb[1] = *(const float4*)&B[(size_t)((k0) + kkB1) * N + n0 + c4B1];  \
        else rb[1] = make_float4(0.f, 0.f, 0.f, 0.f);                           \
    }

#define STS_TILE(buf)                                                           \
    {                                                                           \
        uint4 ua0 = make_uint4(f2tf(ra[0].x), f2tf(ra[0].y), f2tf(ra[0].z), f2tf(ra[0].w)); \
        uint4 ua1 = make_uint4(f2tf(ra[1].x), f2tf(ra[1].y), f2tf(ra[1].z), f2tf(ra[1].w)); \
        *(uint4*)&As[buf][rowA0][kcA0] = ua0;                                   \
        *(uint4*)&As[buf][rowA1][kcA1] = ua1;                                   \
        uint4 ub0 = make_uint4(f2tf(rb[0].x), f2tf(rb[0].y), f2tf(rb[0].z), f2tf(rb[0].w)); \
        uint4 ub1 = make_uint4(f2tf(rb[1].x), f2tf(rb[1].y), f2tf(rb[1].z), f2tf(rb[1].w)); \
        *(uint4*)&Bs[buf][kkB0][c4B0] = ub0;                                    \
        *(uint4*)&Bs[buf][kkB1][c4B1] = ub1;                                    \
    }

#define COMPUTE(buf)                                                            \
    {                                                                           \
        _Pragma("unroll")                                                       \
        for (int ks = 0; ks < 2; ks++) {                                        \
            unsigned af[4][4], bf[4][2];                                        \
            _Pragma("unroll")                                                   \
            for (int mt = 0; mt < 4; mt++) {                                    \
                int mr = wm * 64 + mt * 16 + fr;                                \
                af[mt][0] = As[buf][mr    ][ks * 8 + fc];                       \
                af[mt][1] = As[buf][mr + 8][ks * 8 + fc];                       \
                af[mt][2] = As[buf][mr    ][ks * 8 + fc + 4];                   \
                af[mt][3] = As[buf][mr + 8][ks * 8 + fc + 4];                   \
            }                                                                   \
            _Pragma("unroll")                                                   \
            for (int nt = 0; nt < 4; nt++) {                                    \
                int nc = wn * 32 + nt * 8 + fr;                                 \
                bf[nt][0] = Bs[buf][ks * 8 + fc    ][nc];                       \
                bf[nt][1] = Bs[buf][ks * 8 + fc + 4][nc];                       \
            }                                                                   \
            _Pragma("unroll")                                                   \
            for (int mt = 0; mt < 4; mt++)                                      \
                _Pragma("unroll")                                               \
                for (int nt = 0; nt < 4; nt++)                                  \
                    mma8(acc[mt][nt], af[mt], bf[nt]);                          \
        }                                                                       \
    }

    LDG_TILE(0);
    STS_TILE(0);
    __syncthreads();

    int buf = 0;
#pragma unroll 1
    for (int k0 = 16; k0 < K; k0 += 16) {
        LDG_TILE(k0);
        COMPUTE(buf);
        STS_TILE(buf ^ 1);
        __syncthreads();
        buf ^= 1;
    }
    COMPUTE(buf);

#pragma unroll
    for (int mt = 0; mt < 4; mt++) {
#pragma unroll
        for (int nt = 0; nt < 4; nt++) {
            int row = m0 + wm * 64 + mt * 16 + fr;
            int col = n0 + wn * 32 + nt * 8 + fc * 2;
            float2 v0 = make_float2(acc[mt][nt][0], acc[mt][nt][1]);
            float2 v1 = make_float2(acc[mt][nt][2], acc[mt][nt][3]);
            if (MODE == 0) {
                if (col < N) {
                    *(float2*)&C[(size_t)row * N + col]       = v0;
                    *(float2*)&C[(size_t)(row + 8) * N + col] = v1;
                }
            } else if (MODE == 1) {
                int h = col >> 7, d = col & 127;
                *(float2*)&C[(size_t)((h * S_LEN) + row)     * DQK + d] = v0;
                *(float2*)&C[(size_t)((h * S_LEN) + row + 8) * DQK + d] = v1;
            } else {
                int h = col >> 7, d = col & 127;
                *(float2*)&C[(size_t)((h * S_LEN) + row)     * HD + d] = v0;
                *(float2*)&C[(size_t)((h * S_LEN) + row + 8) * HD + d] = v1;
            }
        }
    }
#undef LDG_TILE
#undef STS_TILE
#undef COMPUTE
}

// ---------------- RoPE -----------------------------------------------------
__global__ void rope_q_kernel()
{
    int idx = blockIdx.x * blockDim.x + threadIdx.x;
    if (idx >= S_LEN * NH * 32) return;
    int i = idx & 31;
    int h = (idx >> 5) & 15;
    int t = idx >> 9;
    float invf = powf(10000.0f, -(2.0f * i) / 64.0f);
    float ang = (float)t * invf;
    float s, c;
    sincosf(ang, &s, &c);
    const float* x = g_qR + (size_t)t * (NH * DR) + h * DR;
    float x1 = x[i], x2 = x[i + 32];
    float* out = g_Qb + (size_t)(h * S_LEN + t) * DQK + HD;
    out[i]      = x1 * c - x2 * s;
    out[i + 32] = x2 * c + x1 * s;
}

__global__ void rope_k_kernel()
{
    int idx = blockIdx.x * blockDim.x + threadIdx.x;
    if (idx >= S_LEN * 32) return;
    int i = idx & 31;
    int t = idx >> 5;
    float invf = powf(10000.0f, -(2.0f * i) / 64.0f);
    float ang = (float)t * invf;
    float s, c;
    sincosf(ang, &s, &c);
    const float* x = g_kR + (size_t)t * DR;
    float r1 = x[i] * c - x[i + 32] * s;
    float r2 = x[i + 32] * c + x[i] * s;
#pragma unroll
    for (int h = 0; h < NH; h++) {
        float* out = g_Kb + (size_t)(h * S_LEN + t) * DQK + HD;
        out[i] = r1;
        out[i + 32] = r2;
    }
}

// ---------------- bf16x3 tensor-core flash attention ------------------------
// BM=128, BN=64, 256 threads / 8 warps arranged 4m x 2n, warp tile 32x32.
// smem byte layout:
//   QH [128][200] bf16 @ 0        (51200)
//   QL               @ 51200
//   KH [64][200]     @ 102400     (25600)
//   KL               @ 128000
//   VTH [128][72]    @ 153600     (18432)   (V transposed: [d][s])
//   VTL              @ 172032
//   red_max [2][128] f32 @ 190464 (1024)
//   red_sum [2][128] f32 @ 191488 (1024)
#define ATTN_SMEM 192512

__global__ __launch_bounds__(256, 1)
void attn_mma_kernel()
{
    extern __shared__ char smraw[];
    unsigned short* QH  = (unsigned short*)(smraw);
    unsigned short* QL  = (unsigned short*)(smraw + 51200);
    unsigned short* KH  = (unsigned short*)(smraw + 102400);
    unsigned short* KL  = (unsigned short*)(smraw + 128000);
    unsigned short* VTH = (unsigned short*)(smraw + 153600);
    unsigned short* VTL = (unsigned short*)(smraw + 172032);
    float* red_max = (float*)(smraw + 190464);
    float* red_sum = (float*)(smraw + 191488);

    const int bid  = blockIdx.x;
    const int mb   = 15 - (bid >> 4);          // heavy blocks first
    const int h    = bid & 15;
    const int m0   = mb * 128;
    const int tid  = threadIdx.x;
    const int lane = tid & 31;
    const int warp = tid >> 5;
    const int wm = warp >> 1, wn = warp & 1;
    const int g = lane >> 2, t = lane & 3;

    const float* Qg = g_Qb + ((size_t)h * S_LEN + m0) * DQK;
    const float* Kg = g_Kb + (size_t)h * S_LEN * DQK;
    const float* Vg = g_Vb + (size_t)h * S_LEN * HD;

    // stage Q (128x192) as bf16 hi/lo
#pragma unroll
    for (int it = 0; it < 24; it++) {
        int idx = tid + it * 256;
        int r = idx / 48, c4 = (idx % 48) * 4;
        float4 v = *(const float4*)&Qg[r * DQK + c4];
        float xs[4] = {v.x, v.y, v.z, v.w};
#pragma unroll
        for (int i = 0; i < 4; i++) {
            int e = r * 200 + c4 + i;
            split2(xs[i], QH[e], QL[e]);
        }
    }

    float oacc[2][16][4];
#pragma unroll
    for (int mt = 0; mt < 2; mt++)
#pragma unroll
        for (int nt = 0; nt < 16; nt++)
#pragma unroll
            for (int c = 0; c < 4; c++) oacc[mt][nt][c] = 0.f;

    float mrow[2][2] = {{-1e30f, -1e30f}, {-1e30f, -1e30f}};
    float lrow[2][2] = {{0.f, 0.f}, {0.f, 0.f}};

    const float scale = 0.07216878364870322f;  // 1/sqrt(192)
    const int ntiles = 2 * mb + 2;

    const int vd = tid & 127;                 // V transpose load: this thread's d
    const int vs0 = (tid >> 7) * 32;

#pragma unroll 1
    for (int tile = 0; tile < ntiles; tile++) {
        const int n0 = tile * 64;
        __syncthreads();   // protect K/V/Q(first iter) from overwrite while in use

        // stage K tile (64x192) hi/lo
#pragma unroll
        for (int it = 0; it < 12; it++) {
            int idx = tid + it * 256;
            int r = idx / 48, c4 = (idx % 48) * 4;
            float4 v = *(const float4*)&Kg[(size_t)(n0 + r) * DQK + c4];
            float xs[4] = {v.x, v.y, v.z, v.w};
#pragma unroll
            for (int i = 0; i < 4; i++) {
                int e = r * 200 + c4 + i;
                split2(xs[i], KH[e], KL[e]);
            }
        }
        // stage V tile transposed [d][s] hi/lo
#pragma unroll
        for (int s8 = 0; s8 < 32; s8++) {
            int s = vs0 + s8;
            float x = Vg[(size_t)(n0 + s) * HD + vd];
            int e = vd * 72 + s;
            split2(x, VTH[e], VTL[e]);
        }
        __syncthreads();

        // ---- S = Q K^T (bf16x3) ----
        float sacc[2][4][4];
#pragma unroll
        for (int mt = 0; mt < 2; mt++)
#pragma unroll
            for (int nt = 0; nt < 4; nt++)
#pragma unroll
                for (int c = 0; c < 4; c++) sacc[mt][nt][c] = 0.f;

#pragma unroll
        for (int kt = 0; kt < 12; kt++) {
            unsigned ah[2][4], al[2][4];
#pragma unroll
            for (int mt = 0; mt < 2; mt++) {
                int rb = (wm * 32 + mt * 16 + g) * 200 + kt * 16 + 2 * t;
                ah[mt][0] = *(const unsigned*)&QH[rb];
                ah[mt][1] = *(const unsigned*)&QH[rb + 1600];
                ah[mt][2] = *(const unsigned*)&QH[rb + 8];
                ah[mt][3] = *(const unsigned*)&QH[rb + 1608];
                al[mt][0] = *(const unsigned*)&QL[rb];
                al[mt][1] = *(const unsigned*)&QL[rb + 1600];
                al[mt][2] = *(const unsigned*)&QL[rb + 8];
                al[mt][3] = *(const unsigned*)&QL[rb + 1608];
            }
#pragma unroll
            for (int nt = 0; nt < 4; nt++) {
                int nb = (wn * 32 + nt * 8 + g) * 200 + kt * 16 + 2 * t;
                unsigned bh[2] = {*(const unsigned*)&KH[nb], *(const unsigned*)&KH[nb + 8]};
                unsigned bl[2] = {*(const unsigned*)&KL[nb], *(const unsigned*)&KL[nb + 8]};
#pragma unroll
                for (int mt = 0; mt < 2; mt++) {
                    mma16(sacc[mt][nt], ah[mt], bh);
                    mma16(sacc[mt][nt], ah[mt], bl);
                    mma16(sacc[mt][nt], al[mt], bh);
                }
            }
        }

        // ---- scale + causal mask ----
#pragma unroll
        for (int mt = 0; mt < 2; mt++)
#pragma unroll
            for (int nt = 0; nt < 4; nt++)
#pragma unroll
                for (int c = 0; c < 4; c++) {
                    int col = n0 + wn * 32 + nt * 8 + 2 * t + (c & 1);
                    int row = m0 + wm * 32 + mt * 16 + g + (c >> 1) * 8;
                    float v = sacc[mt][nt][c] * scale;
                    if (col > row) v = -1e30f;
                    sacc[mt][nt][c] = v;
                }

        // ---- online softmax (cross-wn pair via smem) ----
        float pmv[2][2], alpha_[2][2], psv[2][2];
#pragma unroll
        for (int mt = 0; mt < 2; mt++)
#pragma unroll
            for (int hf = 0; hf < 2; hf++) {
                float pm = -1e30f;
#pragma unroll
                for (int nt = 0; nt < 4; nt++)
                    pm = fmaxf(pm, fmaxf(sacc[mt][nt][hf * 2], sacc[mt][nt][hf * 2 + 1]));
                pm = fmaxf(pm, __shfl_xor_sync(0xffffffffu, pm, 1));
                pm = fmaxf(pm, __shfl_xor_sync(0xffffffffu, pm, 2));
                pmv[mt][hf] = pm;
                if (t == 0) red_max[wn * 128 + wm * 32 + mt * 16 + hf * 8 + g] = pm;
            }
        __syncthreads();
#pragma unroll
        for (int mt = 0; mt < 2; mt++)
#pragma unroll
            for (int hf = 0; hf < 2; hf++) {
                int rowl = wm * 32 + mt * 16 + hf * 8 + g;
                float comb = fmaxf(pmv[mt][hf], red_max[(wn ^ 1) * 128 + rowl]);
                float mnew = fmaxf(mrow[mt][hf], comb);
                alpha_[mt][hf] = __expf(mrow[mt][hf] - mnew);
                mrow[mt][hf] = mnew;
                float ps = 0.f;
#pragma unroll
                for (int nt = 0; nt < 4; nt++)
#pragma unroll
                    for (int k2 = 0; k2 < 2; k2++) {
                        int c = hf * 2 + k2;
                        float p = __expf(sacc[mt][nt][c] - mnew);
                        sacc[mt][nt][c] = p;
                        ps += p;
                    }
                ps += __shfl_xor_sync(0xffffffffu, ps, 1);
                ps += __shfl_xor_sync(0xffffffffu, ps, 2);
                psv[mt][hf] = ps;
                if (t == 0) red_sum[wn * 128 + rowl] = ps;
            }
        __syncthreads();
#pragma unroll
        for (int mt = 0; mt < 2; mt++)
#pragma unroll
            for (int hf = 0; hf < 2; hf++) {
                int rowl = wm * 32 + mt * 16 + hf * 8 + g;
                float tot = psv[mt][hf] + red_sum[(wn ^ 1) * 128 + rowl];
                lrow[mt][hf] = lrow[mt][hf] * alpha_[mt][hf] + tot;
            }
        // rescale O
#pragma unroll
        for (int mt = 0; mt < 2; mt++)
#pragma unroll
            for (int nt = 0; nt < 16; nt++)
#pragma unroll
                for (int c = 0; c < 4; c++)
                    oacc[mt][nt][c] *= alpha_[mt][c >> 1];

        // ---- O += P V (bf16x3; warp's k-slice = cols wn*32..+31) ----
#pragma unroll
        for (int kt2 = 0; kt2 < 2; kt2++) {
            unsigned aph[2][4], apl[2][4];
#pragma unroll
            for (int mt = 0; mt < 2; mt++) {
                aph[mt][0] = packsplit(sacc[mt][2 * kt2][0],     sacc[mt][2 * kt2][1],     apl[mt][0]);
                aph[mt][1] = packsplit(sacc[mt][2 * kt2][2],     sacc[mt][2 * kt2][3],     apl[mt][1]);
                aph[mt][2] = packsplit(sacc[mt][2 * kt2 + 1][0], sacc[mt][2 * kt2 + 1][1], apl[mt][2]);
                aph[mt][3] = packsplit(sacc[mt][2 * kt2 + 1][2], sacc[mt][2 * kt2 + 1][3], apl[mt][3]);
            }
#pragma unroll
            for (int nt = 0; nt < 16; nt++) {
                int vb = (nt * 8 + g) * 72 + wn * 32 + kt2 * 16 + 2 * t;
                unsigned bh[2] = {*(const unsigned*)&VTH[vb], *(const unsigned*)&VTH[vb + 8]};
                unsigned bl[2] = {*(const unsigned*)&VTL[vb], *(const unsigned*)&VTL[vb + 8]};
#pragma unroll
                for (int mt = 0; mt < 2; mt++) {
                    mma16(oacc[mt][nt], aph[mt], bh);
                    mma16(oacc[mt][nt], aph[mt], bl);
                    mma16(oacc[mt][nt], apl[mt], bh);
                }
            }
        }
    }

    // ---- epilogue: sum wn pair partials, divide by l, store ----
    __syncthreads();
    float* osm = (float*)smraw + wm * (32 * 132);   // Q area is dead now
    if (wn == 1) {
#pragma unroll
        for (int mt = 0; mt < 2; mt++)
#pragma unroll
            for (int nt = 0; nt < 16; nt++)
#pragma unroll
                for (int c = 0; c < 4; c++) {
                    int rowl = mt * 16 + (c >> 1) * 8 + g;
                    int col = nt * 8 + 2 * t + (c & 1);
                    osm[rowl * 132 + col] = oacc[mt][nt][c];
                }
    }
    __syncthreads();
    if (wn == 0) {
#pragma unroll
        for (int mt = 0; mt < 2; mt++)
#pragma unroll
            for (int hf = 0; hf < 2; hf++) {
                float inv = 1.f / lrow[mt][hf];
                int rowl = mt * 16 + hf * 8 + g;
                int row = m0 + wm * 32 + rowl;
#pragma unroll
                for (int nt = 0; nt < 16; nt++) {
                    int col = nt * 8 + 2 * t;
                    float v0 = (oacc[mt][nt][hf * 2]     + osm[rowl * 132 + col])     * inv;
                    float v1 = (oacc[mt][nt][hf * 2 + 1] + osm[rowl * 132 + col + 1]) * inv;
                    *(float2*)&g_AO[(size_t)row * (NH * HD) + h * HD + col] = make_float2(v0, v1);
                }
            }
    }
}

// ---------------- launch ----------------------------------------------------
extern "C" void kernel_launch(void* const* d_in, const int* in_sizes, int n_in,
                              void* d_out, int out_size)
{
    const float* X     = (const float*)d_in[0];
    const float* W_DKV = (const float*)d_in[2];
    const float* W_UK  = (const float*)d_in[3];
    const float* W_UV  = (const float*)d_in[4];
    const float* W_DQ  = (const float*)d_in[5];
    const float* W_UQ  = (const float*)d_in[6];
    const float* W_QR  = (const float*)d_in[7];
    const float* W_KR  = (const float*)d_in[8];
    const float* W_O   = (const float*)d_in[9];
    float* out = (float*)d_out;

    float *cKV, *cQ, *Qb, *Kb, *Vb, *qR, *kR, *AO;
    cudaGetSymbolAddress((void**)&cKV, g_cKV);
    cudaGetSymbolAddress((void**)&cQ,  g_cQ);
    cudaGetSymbolAddress((void**)&Qb,  g_Qb);
    cudaGetSymbolAddress((void**)&Kb,  g_Kb);
    cudaGetSymbolAddress((void**)&Vb,  g_Vb);
    cudaGetSymbolAddress((void**)&qR,  g_qR);
    cudaGetSymbolAddress((void**)&kR,  g_kR);
    cudaGetSymbolAddress((void**)&AO,  g_AO);

    dim3 blk(256);
    mma_gemm<0><<<dim3(CKV / 128, S_LEN / 128), blk>>>(X, W_DKV, cKV, S_LEN, CKV, HID_D);
    mma_gemm<1><<<dim3(16, 16), blk>>>(cKV, W_UK, Kb, S_LEN, NH * HD, CKV);
    mma_gemm<2><<<dim3(16, 16), blk>>>(cKV, W_UV, Vb, S_LEN, NH * HD, CKV);
    mma_gemm<0><<<dim3(CQ / 128, 16), blk>>>(X, W_DQ, cQ, S_LEN, CQ, HID_D);
    mma_gemm<1><<<dim3(16, 16), blk>>>(cQ, W_UQ, Qb, S_LEN, NH * HD, CQ);
    mma_gemm<0><<<dim3(NH * DR / 128, 16), blk>>>(cQ, W_QR, qR, S_LEN, NH * DR, CQ);
    mma_gemm<0><<<dim3(1, 16), blk>>>(X, W_KR, kR, S_LEN, DR, HID_D);
    rope_q_kernel<<<(S_LEN * NH * 32) / 256, 256>>>();
    rope_k_kernel<<<(S_LEN * 32) / 256, 256>>>();

    cudaFuncSetAttribute(attn_mma_kernel, cudaFuncAttributeMaxDynamicSharedMemorySize, ATTN_SMEM);
    attn_mma_kernel<<<256, 256, ATTN_SMEM>>>();

    mma_gemm<0><<<dim3(16, 16), blk>>>(AO, W_O, out, S_LEN, HID_D, NH * HD);
}

// round 4
// speedup vs baseline: 4.3181x; 1.3709x over previous
#include <cuda_runtime.h>
#include <cuda_bf16.h>
#include <math.h>

#define S_LEN 2048
#define HID_D 2048
#define NH 16
#define HD 128
#define DR 64
#define DQK 192
#define CKV 512
#define CQ 1536

// ---------------- scratch (static device allocations; no cudaMalloc) -------
__device__ float g_cKV[S_LEN * CKV];
__device__ float g_cQ [S_LEN * CQ];
__device__ float g_Qb [NH * S_LEN * DQK];   // [h][s][192]
__device__ float g_Kb [NH * S_LEN * DQK];   // [h][s][192]
__device__ float g_Vb [NH * S_LEN * HD];    // [h][s][128]
__device__ float g_qR [S_LEN * NH * DR];
__device__ float g_kR [S_LEN * DR];
__device__ float g_AO [S_LEN * NH * HD];    // [s][h*128+d]

// ---------------- tf32 helpers ---------------------------------------------
__device__ __forceinline__ unsigned f2tf(float x) {
    unsigned u;
    asm("cvt.rna.tf32.f32 %0, %1;" : "=r"(u) : "f"(x));
    return u;
}

__device__ __forceinline__ void mma8(float c[4], const unsigned a[4], const unsigned b[2]) {
    asm volatile(
        "mma.sync.aligned.m16n8k8.row.col.f32.tf32.tf32.f32 "
        "{%0,%1,%2,%3}, {%4,%5,%6,%7}, {%8,%9}, {%0,%1,%2,%3};\n"
        : "+f"(c[0]), "+f"(c[1]), "+f"(c[2]), "+f"(c[3])
        : "r"(a[0]), "r"(a[1]), "r"(a[2]), "r"(a[3]), "r"(b[0]), "r"(b[1]));
}

// ---------------- bf16 helpers (attention) ----------------------------------
__device__ __forceinline__ void mma16(float c[4], const unsigned a[4], const unsigned b[2]) {
    asm volatile(
        "mma.sync.aligned.m16n8k16.row.col.f32.bf16.bf16.f32 "
        "{%0,%1,%2,%3}, {%4,%5,%6,%7}, {%8,%9}, {%0,%1,%2,%3};\n"
        : "+f"(c[0]), "+f"(c[1]), "+f"(c[2]), "+f"(c[3])
        : "r"(a[0]), "r"(a[1]), "r"(a[2]), "r"(a[3]), "r"(b[0]), "r"(b[1]));
}

__device__ __forceinline__ void split2(float x, unsigned short &hh, unsigned short &ll) {
    __nv_bfloat16 bh = __float2bfloat16(x);
    float hf = __bfloat162float(bh);
    __nv_bfloat16 bl = __float2bfloat16(x - hf);
    hh = __bfloat16_as_ushort(bh);
    ll = __bfloat16_as_ushort(bl);
}

__device__ __forceinline__ unsigned bfbits(float x) {
    return (unsigned)__bfloat16_as_ushort(__float2bfloat16(x));
}
__device__ __forceinline__ float bfval(float x) {
    return __bfloat162float(__float2bfloat16(x));
}
__device__ __forceinline__ unsigned packsplit(float x, float y, unsigned &lo) {
    float xh = bfval(x), yh = bfval(y);
    unsigned hi = bfbits(x) | (bfbits(y) << 16);
    lo = bfbits(x - xh) | (bfbits(y - yh) << 16);
    return hi;
}

// ---------------- grouped tf32 tensor-core GEMM -----------------------------
// Up to 4 groups per launch; each group: C = A[2048 x K] @ B[K x N].
// blockIdx.x selects group via tstart[]; blockIdx.y = m-tile (128 rows).
// mode 0: row-major C [M,N] (col<N guarded)
// mode 1: head-split 192-stride   mode 2: head-split 128-stride
struct GroupArgs {
    const float* A[4];
    const float* B[4];
    float*       C[4];
    int K[4];
    int N[4];
    int mode[4];
    int tstart[5];
};

__global__ __launch_bounds__(256, 2)
void mma_gemm_grouped(GroupArgs ga)
{
    __shared__ unsigned As[2][128][20];
    __shared__ unsigned Bs[2][16][136];

    int g = 0;
    while (blockIdx.x >= (unsigned)ga.tstart[g + 1]) g++;
    const float* __restrict__ A = ga.A[g];
    const float* __restrict__ B = ga.B[g];
    float* __restrict__ C = ga.C[g];
    const int K = ga.K[g];
    const int N = ga.N[g];
    const int mode = ga.mode[g];

    const int tid  = threadIdx.x;
    const int lane = tid & 31;
    const int warp = tid >> 5;
    const int wm   = warp & 1;
    const int wn   = warp >> 1;
    const int m0   = blockIdx.y * 128;
    const int n0   = (blockIdx.x - ga.tstart[g]) * 128;
    const int fr   = lane >> 2;
    const int fc   = lane & 3;

    float acc[4][4][4];
#pragma unroll
    for (int mt = 0; mt < 4; mt++)
#pragma unroll
        for (int nt = 0; nt < 4; nt++)
#pragma unroll
            for (int i = 0; i < 4; i++) acc[mt][nt][i] = 0.f;

    float4 ra[2], rb[2];

    const int rowA0 = (tid + 0)   >> 2;   const int kcA0 = ((tid + 0)   & 3) * 4;
    const int rowA1 = (tid + 256) >> 2;   const int kcA1 = ((tid + 256) & 3) * 4;
    const int kkB0  = (tid + 0)   >> 5;   const int c4B0 = ((tid + 0)   & 31) * 4;
    const int kkB1  = (tid + 256) >> 5;   const int c4B1 = ((tid + 256) & 31) * 4;

#define LDG_TILE(k0)                                                            \
    {                                                                           \
        ra[0] = *(const float4*)&A[(size_t)(m0 + rowA0) * K + (k0) + kcA0];     \
        ra[1] = *(const float4*)&A[(size_t)(m0 + rowA1) * K + (k0) + kcA1];     \
        if (n0 + c4B0 < N)                                                      \
            rb[0] = *(const float4*)&B[(size_t)((k0) + kkB0) * N + n0 + c4B0];  \
        else rb[0] = make_float4(0.f, 0.f, 0.f, 0.f);                           \
        if (n0 + c4B1 < N)                                                      \
            rb[1] = *(const float4*)&B[(size_t)((k0) + kkB1) * N + n0 + c4B1];  \
        else rb[1] = make_float4(0.f, 0.f, 0.f, 0.f);                           \
    }

#define STS_TILE(buf)                                                           \
    {                                                                           \
        uint4 ua0 = make_uint4(f2tf(ra[0].x), f2tf(ra[0].y), f2tf(ra[0].z), f2tf(ra[0].w)); \
        uint4 ua1 = make_uint4(f2tf(ra[1].x), f2tf(ra[1].y), f2tf(ra[1].z), f2tf(ra[1].w)); \
        *(uint4*)&As[buf][rowA0][kcA0] = ua0;                                   \
        *(uint4*)&As[buf][rowA1][kcA1] = ua1;                                   \
        uint4 ub0 = make_uint4(f2tf(rb[0].x), f2tf(rb[0].y), f2tf(rb[0].z), f2tf(rb[0].w)); \
        uint4 ub1 = make_uint4(f2tf(rb[1].x), f2tf(rb[1].y), f2tf(rb[1].z), f2tf(rb[1].w)); \
        *(uint4*)&Bs[buf][kkB0][c4B0] = ub0;                                    \
        *(uint4*)&Bs[buf][kkB1][c4B1] = ub1;                                    \
    }

#define COMPUTE(buf)                                                            \
    {                                                                           \
        _Pragma("unroll")                                                       \
        for (int ks = 0; ks < 2; ks++) {                                        \
            unsigned af[4][4], bf[4][2];                                        \
            _Pragma("unroll")                                                   \
            for (int mt = 0; mt < 4; mt++) {                                    \
                int mr = wm * 64 + mt * 16 + fr;                                \
                af[mt][0] = As[buf][mr    ][ks * 8 + fc];                       \
                af[mt][1] = As[buf][mr + 8][ks * 8 + fc];                       \
                af[mt][2] = As[buf][mr    ][ks * 8 + fc + 4];                   \
                af[mt][3] = As[buf][mr + 8][ks * 8 + fc + 4];                   \
            }                                                                   \
            _Pragma("unroll")                                                   \
            for (int nt = 0; nt < 4; nt++) {                                    \
                int nc = wn * 32 + nt * 8 + fr;                                 \
                bf[nt][0] = Bs[buf][ks * 8 + fc    ][nc];                       \
                bf[nt][1] = Bs[buf][ks * 8 + fc + 4][nc];                       \
            }                                                                   \
            _Pragma("unroll")                                                   \
            for (int mt = 0; mt < 4; mt++)                                      \
                _Pragma("unroll")                                               \
                for (int nt = 0; nt < 4; nt++)                                  \
                    mma8(acc[mt][nt], af[mt], bf[nt]);                          \
        }                                                                       \
    }

    LDG_TILE(0);
    STS_TILE(0);
    __syncthreads();

    int buf = 0;
#pragma unroll 1
    for (int k0 = 16; k0 < K; k0 += 16) {
        LDG_TILE(k0);
        COMPUTE(buf);
        STS_TILE(buf ^ 1);
        __syncthreads();
        buf ^= 1;
    }
    COMPUTE(buf);

#pragma unroll
    for (int mt = 0; mt < 4; mt++) {
#pragma unroll
        for (int nt = 0; nt < 4; nt++) {
            int row = m0 + wm * 64 + mt * 16 + fr;
            int col = n0 + wn * 32 + nt * 8 + fc * 2;
            float2 v0 = make_float2(acc[mt][nt][0], acc[mt][nt][1]);
            float2 v1 = make_float2(acc[mt][nt][2], acc[mt][nt][3]);
            if (mode == 0) {
                if (col < N) {
                    *(float2*)&C[(size_t)row * N + col]       = v0;
                    *(float2*)&C[(size_t)(row + 8) * N + col] = v1;
                }
            } else if (mode == 1) {
                int h = col >> 7, d = col & 127;
                *(float2*)&C[(size_t)((h * S_LEN) + row)     * DQK + d] = v0;
                *(float2*)&C[(size_t)((h * S_LEN) + row + 8) * DQK + d] = v1;
            } else {
                int h = col >> 7, d = col & 127;
                *(float2*)&C[(size_t)((h * S_LEN) + row)     * HD + d] = v0;
                *(float2*)&C[(size_t)((h * S_LEN) + row + 8) * HD + d] = v1;
            }
        }
    }
#undef LDG_TILE
#undef STS_TILE
#undef COMPUTE
}

// ---------------- RoPE -----------------------------------------------------
__global__ void rope_q_kernel()
{
    int idx = blockIdx.x * blockDim.x + threadIdx.x;
    if (idx >= S_LEN * NH * 32) return;
    int i = idx & 31;
    int h = (idx >> 5) & 15;
    int t = idx >> 9;
    float invf = powf(10000.0f, -(2.0f * i) / 64.0f);
    float ang = (float)t * invf;
    float s, c;
    sincosf(ang, &s, &c);
    const float* x = g_qR + (size_t)t * (NH * DR) + h * DR;
    float x1 = x[i], x2 = x[i + 32];
    float* out = g_Qb + (size_t)(h * S_LEN + t) * DQK + HD;
    out[i]      = x1 * c - x2 * s;
    out[i + 32] = x2 * c + x1 * s;
}

__global__ void rope_k_kernel()
{
    int idx = blockIdx.x * blockDim.x + threadIdx.x;
    if (idx >= S_LEN * 32) return;
    int i = idx & 31;
    int t = idx >> 5;
    float invf = powf(10000.0f, -(2.0f * i) / 64.0f);
    float ang = (float)t * invf;
    float s, c;
    sincosf(ang, &s, &c);
    const float* x = g_kR + (size_t)t * DR;
    float r1 = x[i] * c - x[i + 32] * s;
    float r2 = x[i + 32] * c + x[i] * s;
#pragma unroll
    for (int h = 0; h < NH; h++) {
        float* out = g_Kb + (size_t)(h * S_LEN + t) * DQK + HD;
        out[i] = r1;
        out[i + 32] = r2;
    }
}

// ---------------- bf16x3 tensor-core flash attention (unchanged) ------------
#define ATTN_SMEM 192512

__global__ __launch_bounds__(256, 1)
void attn_mma_kernel()
{
    extern __shared__ char smraw[];
    unsigned short* QH  = (unsigned short*)(smraw);
    unsigned short* QL  = (unsigned short*)(smraw + 51200);
    unsigned short* KH  = (unsigned short*)(smraw + 102400);
    unsigned short* KL  = (unsigned short*)(smraw + 128000);
    unsigned short* VTH = (unsigned short*)(smraw + 153600);
    unsigned short* VTL = (unsigned short*)(smraw + 172032);
    float* red_max = (float*)(smraw + 190464);
    float* red_sum = (float*)(smraw + 191488);

    const int bid  = blockIdx.x;
    const int mb   = 15 - (bid >> 4);
    const int h    = bid & 15;
    const int m0   = mb * 128;
    const int tid  = threadIdx.x;
    const int lane = tid & 31;
    const int warp = tid >> 5;
    const int wm = warp >> 1, wn = warp & 1;
    const int g = lane >> 2, t = lane & 3;

    const float* Qg = g_Qb + ((size_t)h * S_LEN + m0) * DQK;
    const float* Kg = g_Kb + (size_t)h * S_LEN * DQK;
    const float* Vg = g_Vb + (size_t)h * S_LEN * HD;

#pragma unroll
    for (int it = 0; it < 24; it++) {
        int idx = tid + it * 256;
        int r = idx / 48, c4 = (idx % 48) * 4;
        float4 v = *(const float4*)&Qg[r * DQK + c4];
        float xs[4] = {v.x, v.y, v.z, v.w};
#pragma unroll
        for (int i = 0; i < 4; i++) {
            int e = r * 200 + c4 + i;
            split2(xs[i], QH[e], QL[e]);
        }
    }

    float oacc[2][16][4];
#pragma unroll
    for (int mt = 0; mt < 2; mt++)
#pragma unroll
        for (int nt = 0; nt < 16; nt++)
#pragma unroll
            for (int c = 0; c < 4; c++) oacc[mt][nt][c] = 0.f;

    float mrow[2][2] = {{-1e30f, -1e30f}, {-1e30f, -1e30f}};
    float lrow[2][2] = {{0.f, 0.f}, {0.f, 0.f}};

    const float scale = 0.07216878364870322f;
    const int ntiles = 2 * mb + 2;

    const int vd = tid & 127;
    const int vs0 = (tid >> 7) * 32;

#pragma unroll 1
    for (int tile = 0; tile < ntiles; tile++) {
        const int n0 = tile * 64;
        __syncthreads();

#pragma unroll
        for (int it = 0; it < 12; it++) {
            int idx = tid + it * 256;
            int r = idx / 48, c4 = (idx % 48) * 4;
            float4 v = *(const float4*)&Kg[(size_t)(n0 + r) * DQK + c4];
            float xs[4] = {v.x, v.y, v.z, v.w};
#pragma unroll
            for (int i = 0; i < 4; i++) {
                int e = r * 200 + c4 + i;
                split2(xs[i], KH[e], KL[e]);
            }
        }
#pragma unroll
        for (int s8 = 0; s8 < 32; s8++) {
            int s = vs0 + s8;
            float x = Vg[(size_t)(n0 + s) * HD + vd];
            int e = vd * 72 + s;
            split2(x, VTH[e], VTL[e]);
        }
        __syncthreads();

        float sacc[2][4][4];
#pragma unroll
        for (int mt = 0; mt < 2; mt++)
#pragma unroll
            for (int nt = 0; nt < 4; nt++)
#pragma unroll
                for (int c = 0; c < 4; c++) sacc[mt][nt][c] = 0.f;

#pragma unroll
        for (int kt = 0; kt < 12; kt++) {
            unsigned ah[2][4], al[2][4];
#pragma unroll
            for (int mt = 0; mt < 2; mt++) {
                int rb = (wm * 32 + mt * 16 + g) * 200 + kt * 16 + 2 * t;
                ah[mt][0] = *(const unsigned*)&QH[rb];
                ah[mt][1] = *(const unsigned*)&QH[rb + 1600];
                ah[mt][2] = *(const unsigned*)&QH[rb + 8];
                ah[mt][3] = *(const unsigned*)&QH[rb + 1608];
                al[mt][0] = *(const unsigned*)&QL[rb];
                al[mt][1] = *(const unsigned*)&QL[rb + 1600];
                al[mt][2] = *(const unsigned*)&QL[rb + 8];
                al[mt][3] = *(const unsigned*)&QL[rb + 1608];
            }
#pragma unroll
            for (int nt = 0; nt < 4; nt++) {
                int nb = (wn * 32 + nt * 8 + g) * 200 + kt * 16 + 2 * t;
                unsigned bh[2] = {*(const unsigned*)&KH[nb], *(const unsigned*)&KH[nb + 8]};
                unsigned bl[2] = {*(const unsigned*)&KL[nb], *(const unsigned*)&KL[nb + 8]};
#pragma unroll
                for (int mt = 0; mt < 2; mt++) {
                    mma16(sacc[mt][nt], ah[mt], bh);
                    mma16(sacc[mt][nt], ah[mt], bl);
                    mma16(sacc[mt][nt], al[mt], bh);
                }
            }
        }

#pragma unroll
        for (int mt = 0; mt < 2; mt++)
#pragma unroll
            for (int nt = 0; nt < 4; nt++)
#pragma unroll
                for (int c = 0; c < 4; c++) {
                    int col = n0 + wn * 32 + nt * 8 + 2 * t + (c & 1);
                    int row = m0 + wm * 32 + mt * 16 + g + (c >> 1) * 8;
                    float v = sacc[mt][nt][c] * scale;
                    if (col > row) v = -1e30f;
                    sacc[mt][nt][c] = v;
                }

        float pmv[2][2], alpha_[2][2], psv[2][2];
#pragma unroll
        for (int mt = 0; mt < 2; mt++)
#pragma unroll
            for (int hf = 0; hf < 2; hf++) {
                float pm = -1e30f;
#pragma unroll
                for (int nt = 0; nt < 4; nt++)
                    pm = fmaxf(pm, fmaxf(sacc[mt][nt][hf * 2], sacc[mt][nt][hf * 2 + 1]));
                pm = fmaxf(pm, __shfl_xor_sync(0xffffffffu, pm, 1));
                pm = fmaxf(pm, __shfl_xor_sync(0xffffffffu, pm, 2));
                pmv[mt][hf] = pm;
                if (t == 0) red_max[wn * 128 + wm * 32 + mt * 16 + hf * 8 + g] = pm;
            }
        __syncthreads();
#pragma unroll
        for (int mt = 0; mt < 2; mt++)
#pragma unroll
            for (int hf = 0; hf < 2; hf++) {
                int rowl = wm * 32 + mt * 16 + hf * 8 + g;
                float comb = fmaxf(pmv[mt][hf], red_max[(wn ^ 1) * 128 + rowl]);
                float mnew = fmaxf(mrow[mt][hf], comb);
                alpha_[mt][hf] = __expf(mrow[mt][hf] - mnew);
                mrow[mt][hf] = mnew;
                float ps = 0.f;
#pragma unroll
                for (int nt = 0; nt < 4; nt++)
#pragma unroll
                    for (int k2 = 0; k2 < 2; k2++) {
                        int c = hf * 2 + k2;
                        float p = __expf(sacc[mt][nt][c] - mnew);
                        sacc[mt][nt][c] = p;
                        ps += p;
                    }
                ps += __shfl_xor_sync(0xffffffffu, ps, 1);
                ps += __shfl_xor_sync(0xffffffffu, ps, 2);
                psv[mt][hf] = ps;
                if (t == 0) red_sum[wn * 128 + rowl] = ps;
            }
        __syncthreads();
#pragma unroll
        for (int mt = 0; mt < 2; mt++)
#pragma unroll
            for (int hf = 0; hf < 2; hf++) {
                int rowl = wm * 32 + mt * 16 + hf * 8 + g;
                float tot = psv[mt][hf] + red_sum[(wn ^ 1) * 128 + rowl];
                lrow[mt][hf] = lrow[mt][hf] * alpha_[mt][hf] + tot;
            }
#pragma unroll
        for (int mt = 0; mt < 2; mt++)
#pragma unroll
            for (int nt = 0; nt < 16; nt++)
#pragma unroll
                for (int c = 0; c < 4; c++)
                    oacc[mt][nt][c] *= alpha_[mt][c >> 1];

#pragma unroll
        for (int kt2 = 0; kt2 < 2; kt2++) {
            unsigned aph[2][4], apl[2][4];
#pragma unroll
            for (int mt = 0; mt < 2; mt++) {
                aph[mt][0] = packsplit(sacc[mt][2 * kt2][0],     sacc[mt][2 * kt2][1],     apl[mt][0]);
                aph[mt][1] = packsplit(sacc[mt][2 * kt2][2],     sacc[mt][2 * kt2][3],     apl[mt][1]);
                aph[mt][2] = packsplit(sacc[mt][2 * kt2 + 1][0], sacc[mt][2 * kt2 + 1][1], apl[mt][2]);
                aph[mt][3] = packsplit(sacc[mt][2 * kt2 + 1][2], sacc[mt][2 * kt2 + 1][3], apl[mt][3]);
            }
#pragma unroll
            for (int nt = 0; nt < 16; nt++) {
                int vb = (nt * 8 + g) * 72 + wn * 32 + kt2 * 16 + 2 * t;
                unsigned bh[2] = {*(const unsigned*)&VTH[vb], *(const unsigned*)&VTH[vb + 8]};
                unsigned bl[2] = {*(const unsigned*)&VTL[vb], *(const unsigned*)&VTL[vb + 8]};
#pragma unroll
                for (int mt = 0; mt < 2; mt++) {
                    mma16(oacc[mt][nt], aph[mt], bh);
                    mma16(oacc[mt][nt], aph[mt], bl);
                    mma16(oacc[mt][nt], apl[mt], bh);
                }
            }
        }
    }

    __syncthreads();
    float* osm = (float*)smraw + wm * (32 * 132);
    if (wn == 1) {
#pragma unroll
        for (int mt = 0; mt < 2; mt++)
#pragma unroll
            for (int nt = 0; nt < 16; nt++)
#pragma unroll
                for (int c = 0; c < 4; c++) {
                    int rowl = mt * 16 + (c >> 1) * 8 + g;
                    int col = nt * 8 + 2 * t + (c & 1);
                    osm[rowl * 132 + col] = oacc[mt][nt][c];
                }
    }
    __syncthreads();
    if (wn == 0) {
#pragma unroll
        for (int mt = 0; mt < 2; mt++)
#pragma unroll
            for (int hf = 0; hf < 2; hf++) {
                float inv = 1.f / lrow[mt][hf];
                int rowl = mt * 16 + hf * 8 + g;
                int row = m0 + wm * 32 + rowl;
#pragma unroll
                for (int nt = 0; nt < 16; nt++) {
                    int col = nt * 8 + 2 * t;
                    float v0 = (oacc[mt][nt][hf * 2]     + osm[rowl * 132 + col])     * inv;
                    float v1 = (oacc[mt][nt][hf * 2 + 1] + osm[rowl * 132 + col + 1]) * inv;
                    *(float2*)&g_AO[(size_t)row * (NH * HD) + h * HD + col] = make_float2(v0, v1);
                }
            }
    }
}

// ---------------- launch ----------------------------------------------------
extern "C" void kernel_launch(void* const* d_in, const int* in_sizes, int n_in,
                              void* d_out, int out_size)
{
    const float* X     = (const float*)d_in[0];
    const float* W_DKV = (const float*)d_in[2];
    const float* W_UK  = (const float*)d_in[3];
    const float* W_UV  = (const float*)d_in[4];
    const float* W_DQ  = (const float*)d_in[5];
    const float* W_UQ  = (const float*)d_in[6];
    const float* W_QR  = (const float*)d_in[7];
    const float* W_KR  = (const float*)d_in[8];
    const float* W_O   = (const float*)d_in[9];
    float* out = (float*)d_out;

    float *cKV, *cQ, *Qb, *Kb, *Vb, *qR, *kR, *AO;
    cudaGetSymbolAddress((void**)&cKV, g_cKV);
    cudaGetSymbolAddress((void**)&cQ,  g_cQ);
    cudaGetSymbolAddress((void**)&Qb,  g_Qb);
    cudaGetSymbolAddress((void**)&Kb,  g_Kb);
    cudaGetSymbolAddress((void**)&Vb,  g_Vb);
    cudaGetSymbolAddress((void**)&qR,  g_qR);
    cudaGetSymbolAddress((void**)&kR,  g_kR);
    cudaGetSymbolAddress((void**)&AO,  g_AO);

    dim3 blk(256);

    // P1: X @ {W_DQ, W_DKV, W_KR}  (K=2048 uniform; 12+4+1 = 17 n-tiles)
    {
        GroupArgs ga = {};
        ga.A[0] = X;  ga.B[0] = W_DQ;  ga.C[0] = cQ;  ga.K[0] = HID_D; ga.N[0] = CQ;   ga.mode[0] = 0;
        ga.A[1] = X;  ga.B[1] = W_DKV; ga.C[1] = cKV; ga.K[1] = HID_D; ga.N[1] = CKV;  ga.mode[1] = 0;
        ga.A[2] = X;  ga.B[2] = W_KR;  ga.C[2] = kR;  ga.K[2] = HID_D; ga.N[2] = DR;   ga.mode[2] = 0;
        ga.tstart[0] = 0; ga.tstart[1] = 12; ga.tstart[2] = 16; ga.tstart[3] = 17; ga.tstart[4] = 17;
        mma_gemm_grouped<<<dim3(17, 16), blk>>>(ga);
    }
    // P2: up-projections {UQ, QR, UK, UV} (long-K groups first; 16+8+16+16 = 56 tiles)
    {
        GroupArgs ga = {};
        ga.A[0] = cQ;  ga.B[0] = W_UQ; ga.C[0] = Qb; ga.K[0] = CQ;  ga.N[0] = NH * HD; ga.mode[0] = 1;
        ga.A[1] = cQ;  ga.B[1] = W_QR; ga.C[1] = qR; ga.K[1] = CQ;  ga.N[1] = NH * DR; ga.mode[1] = 0;
        ga.A[2] = cKV; ga.B[2] = W_UK; ga.C[2] = Kb; ga.K[2] = CKV; ga.N[2] = NH * HD; ga.mode[2] = 1;
        ga.A[3] = cKV; ga.B[3] = W_UV; ga.C[3] = Vb; ga.K[3] = CKV; ga.N[3] = NH * HD; ga.mode[3] = 2;
        ga.tstart[0] = 0; ga.tstart[1] = 16; ga.tstart[2] = 24; ga.tstart[3] = 40; ga.tstart[4] = 56;
        mma_gemm_grouped<<<dim3(56, 16), blk>>>(ga);
    }

    rope_q_kernel<<<(S_LEN * NH * 32) / 256, 256>>>();
    rope_k_kernel<<<(S_LEN * 32) / 256, 256>>>();

    cudaFuncSetAttribute(attn_mma_kernel, cudaFuncAttributeMaxDynamicSharedMemorySize, ATTN_SMEM);
    attn_mma_kernel<<<256, 256, ATTN_SMEM>>>();

    // out = AO @ W_O
    {
        GroupArgs ga = {};
        ga.A[0] = AO; ga.B[0] = W_O; ga.C[0] = out; ga.K[0] = NH * HD; ga.N[0] = HID_D; ga.mode[0] = 0;
        ga.tstart[0] = 0; ga.tstart[1] = 16; ga.tstart[2] = 16; ga.tstart[3] = 16; ga.tstart[4] = 16;
        mma_gemm_grouped<<<dim3(16, 16), blk>>>(ga);
    }
}

// round 5
// speedup vs baseline: 4.4928x; 1.0405x over previous
#include <cuda_runtime.h>
#include <cuda_bf16.h>
#include <math.h>

#define S_LEN 2048
#define HID_D 2048
#define NH 16
#define HD 128
#define DR 64
#define DQK 192
#define CKV 512
#define CQ 1536

// ---------------- scratch (static device allocations; no cudaMalloc) -------
__device__ float g_cKV[S_LEN * CKV];
__device__ float g_cQ [S_LEN * CQ];
__device__ float g_qR [S_LEN * NH * DR];
__device__ float g_kR [S_LEN * DR];
__device__ float g_Vb [NH * S_LEN * HD];      // [h][s][128] f32 (pre-transpose)
__device__ float g_AO [S_LEN * NH * HD];      // [s][h*128+d]
__device__ unsigned short g_QH[NH * S_LEN * DQK];   // bf16 hi, [h][s][192]
__device__ unsigned short g_QL[NH * S_LEN * DQK];   // bf16 lo
__device__ unsigned short g_KH[NH * S_LEN * DQK];
__device__ unsigned short g_KL[NH * S_LEN * DQK];
__device__ unsigned short g_VTH[NH * HD * S_LEN];   // bf16 hi, [h][d][s]
__device__ unsigned short g_VTL[NH * HD * S_LEN];

// ---------------- tf32 helpers ---------------------------------------------
__device__ __forceinline__ unsigned f2tf(float x) {
    unsigned u;
    asm("cvt.rna.tf32.f32 %0, %1;" : "=r"(u) : "f"(x));
    return u;
}

__device__ __forceinline__ void mma8(float c[4], const unsigned a[4], const unsigned b[2]) {
    asm volatile(
        "mma.sync.aligned.m16n8k8.row.col.f32.tf32.tf32.f32 "
        "{%0,%1,%2,%3}, {%4,%5,%6,%7}, {%8,%9}, {%0,%1,%2,%3};\n"
        : "+f"(c[0]), "+f"(c[1]), "+f"(c[2]), "+f"(c[3])
        : "r"(a[0]), "r"(a[1]), "r"(a[2]), "r"(a[3]), "r"(b[0]), "r"(b[1]));
}

// ---------------- bf16 helpers ----------------------------------------------
__device__ __forceinline__ void mma16(float c[4], const unsigned a[4], const unsigned b[2]) {
    asm volatile(
        "mma.sync.aligned.m16n8k16.row.col.f32.bf16.bf16.f32 "
        "{%0,%1,%2,%3}, {%4,%5,%6,%7}, {%8,%9}, {%0,%1,%2,%3};\n"
        : "+f"(c[0]), "+f"(c[1]), "+f"(c[2]), "+f"(c[3])
        : "r"(a[0]), "r"(a[1]), "r"(a[2]), "r"(a[3]), "r"(b[0]), "r"(b[1]));
}

__device__ __forceinline__ void split2(float x, unsigned short &hh, unsigned short &ll) {
    __nv_bfloat16 bh = __float2bfloat16(x);
    float hf = __bfloat162float(bh);
    __nv_bfloat16 bl = __float2bfloat16(x - hf);
    hh = __bfloat16_as_ushort(bh);
    ll = __bfloat16_as_ushort(bl);
}

__device__ __forceinline__ unsigned bfbits(float x) {
    return (unsigned)__bfloat16_as_ushort(__float2bfloat16(x));
}
__device__ __forceinline__ float bfval(float x) {
    return __bfloat162float(__float2bfloat16(x));
}
__device__ __forceinline__ unsigned packsplit(float x, float y, unsigned &lo) {
    float xh = bfval(x), yh = bfval(y);
    unsigned hi = bfbits(x) | (bfbits(y) << 16);
    lo = bfbits(x - xh) | (bfbits(y - yh) << 16);
    return hi;
}

// ---------------- grouped tf32 tensor-core GEMM -----------------------------
// blockIdx.y selects group/n-tile (long-K groups first), blockIdx.x = m-tile.
// mode 0: row-major f32 C [M,N] (col<N guarded)
// mode 1: head-split 192-stride bf16 hi/lo pair (C, Clo)
// mode 2: head-split 128-stride f32
struct GroupArgs {
    const float* A[4];
    const float* B[4];
    void*        C[4];
    void*        Clo[4];
    int K[4];
    int N[4];
    int mode[4];
    int tstart[5];
};

__global__ __launch_bounds__(256, 2)
void mma_gemm_grouped(GroupArgs ga)
{
    __shared__ unsigned As[2][128][20];
    __shared__ unsigned Bs[2][16][136];

    int g = 0;
    while (blockIdx.y >= (unsigned)ga.tstart[g + 1]) g++;
    const float* __restrict__ A = ga.A[g];
    const float* __restrict__ B = ga.B[g];
    const int K = ga.K[g];
    const int N = ga.N[g];
    const int mode = ga.mode[g];

    const int tid  = threadIdx.x;
    const int lane = tid & 31;
    const int warp = tid >> 5;
    const int wm   = warp & 1;
    const int wn   = warp >> 1;
    const int m0   = blockIdx.x * 128;
    const int n0   = (blockIdx.y - ga.tstart[g]) * 128;
    const int fr   = lane >> 2;
    const int fc   = lane & 3;

    float acc[4][4][4];
#pragma unroll
    for (int mt = 0; mt < 4; mt++)
#pragma unroll
        for (int nt = 0; nt < 4; nt++)
#pragma unroll
            for (int i = 0; i < 4; i++) acc[mt][nt][i] = 0.f;

    float4 ra[2], rb[2];

    const int rowA0 = (tid + 0)   >> 2;   const int kcA0 = ((tid + 0)   & 3) * 4;
    const int rowA1 = (tid + 256) >> 2;   const int kcA1 = ((tid + 256) & 3) * 4;
    const int kkB0  = (tid + 0)   >> 5;   const int c4B0 = ((tid + 0)   & 31) * 4;
    const int kkB1  = (tid + 256) >> 5;   const int c4B1 = ((tid + 256) & 31) * 4;

#define LDG_TILE(k0)                                                            \
    {                                                                           \
        ra[0] = *(const float4*)&A[(size_t)(m0 + rowA0) * K + (k0) + kcA0];     \
        ra[1] = *(const float4*)&A[(size_t)(m0 + rowA1) * K + (k0) + kcA1];     \
        if (n0 + c4B0 < N)                                                      \
            rb[0] = *(const float4*)&B[(size_t)((k0) + kkB0) * N + n0 + c4B0];  \
        else rb[0] = make_float4(0.f, 0.f, 0.f, 0.f);                           \
        if (n0 + c4B1 < N)                                                      \
            rb[1] = *(const float4*)&B[(size_t)((k0) + kkB1) * N + n0 + c4B1];  \
        else rb[1] = make_float4(0.f, 0.f, 0.f, 0.f);                           \
    }

#define STS_TILE(buf)                                                           \
    {                                                                           \
        uint4 ua0 = make_uint4(f2tf(ra[0].x), f2tf(ra[0].y), f2tf(ra[0].z), f2tf(ra[0].w)); \
        uint4 ua1 = make_uint4(f2tf(ra[1].x), f2tf(ra[1].y), f2tf(ra[1].z), f2tf(ra[1].w)); \
        *(uint4*)&As[buf][rowA0][kcA0] = ua0;                                   \
        *(uint4*)&As[buf][rowA1][kcA1] = ua1;                                   \
        uint4 ub0 = make_uint4(f2tf(rb[0].x), f2tf(rb[0].y), f2tf(rb[0].z), f2tf(rb[0].w)); \
        uint4 ub1 = make_uint4(f2tf(rb[1].x), f2tf(rb[1].y), f2tf(rb[1].z), f2tf(rb[1].w)); \
        *(uint4*)&Bs[buf][kkB0][c4B0] = ub0;                                    \
        *(uint4*)&Bs[buf][kkB1][c4B1] = ub1;                                    \
    }

#define COMPUTE(buf)                                                            \
    {                                                                           \
        _Pragma("unroll")                                                       \
        for (int ks = 0; ks < 2; ks++) {                                        \
            unsigned af[4][4], bf[4][2];                                        \
            _Pragma("unroll")                                                   \
            for (int mt = 0; mt < 4; mt++) {                                    \
                int mr = wm * 64 + mt * 16 + fr;                                \
                af[mt][0] = As[buf][mr    ][ks * 8 + fc];                       \
                af[mt][1] = As[buf][mr + 8][ks * 8 + fc];                       \
                af[mt][2] = As[buf][mr    ][ks * 8 + fc + 4];                   \
                af[mt][3] = As[buf][mr + 8][ks * 8 + fc + 4];                   \
            }                                                                   \
            _Pragma("unroll")                                                   \
            for (int nt = 0; nt < 4; nt++) {                                    \
                int nc = wn * 32 + nt * 8 + fr;                                 \
                bf[nt][0] = Bs[buf][ks * 8 + fc    ][nc];                       \
                bf[nt][1] = Bs[buf][ks * 8 + fc + 4][nc];                       \
            }                                                                   \
            _Pragma("unroll")                                                   \
            for (int mt = 0; mt < 4; mt++)                                      \
                _Pragma("unroll")                                               \
                for (int nt = 0; nt < 4; nt++)                                  \
                    mma8(acc[mt][nt], af[mt], bf[nt]);                          \
        }                                                                       \
    }

    LDG_TILE(0);
    STS_TILE(0);
    __syncthreads();

    int buf = 0;
#pragma unroll 1
    for (int k0 = 16; k0 < K; k0 += 16) {
        LDG_TILE(k0);
        COMPUTE(buf);
        STS_TILE(buf ^ 1);
        __syncthreads();
        buf ^= 1;
    }
    COMPUTE(buf);

#pragma unroll
    for (int mt = 0; mt < 4; mt++) {
#pragma unroll
        for (int nt = 0; nt < 4; nt++) {
            int row = m0 + wm * 64 + mt * 16 + fr;
            int col = n0 + wn * 32 + nt * 8 + fc * 2;
            if (mode == 0) {
                float* Cf = (float*)ga.C[g];
                if (col < N) {
                    *(float2*)&Cf[(size_t)row * N + col] =
                        make_float2(acc[mt][nt][0], acc[mt][nt][1]);
                    *(float2*)&Cf[(size_t)(row + 8) * N + col] =
                        make_float2(acc[mt][nt][2], acc[mt][nt][3]);
                }
            } else if (mode == 1) {
                unsigned short* CH = (unsigned short*)ga.C[g];
                unsigned short* CL = (unsigned short*)ga.Clo[g];
                int hh = col >> 7, d = col & 127;
                size_t b0 = ((size_t)(hh * S_LEN + row)) * DQK + d;
                size_t b1 = ((size_t)(hh * S_LEN + row + 8)) * DQK + d;
                unsigned lo, hi;
                hi = packsplit(acc[mt][nt][0], acc[mt][nt][1], lo);
                *(unsigned*)&CH[b0] = hi; *(unsigned*)&CL[b0] = lo;
                hi = packsplit(acc[mt][nt][2], acc[mt][nt][3], lo);
                *(unsigned*)&CH[b1] = hi; *(unsigned*)&CL[b1] = lo;
            } else {
                float* Cf = (float*)ga.C[g];
                int hh = col >> 7, d = col & 127;
                *(float2*)&Cf[(size_t)((hh * S_LEN) + row)     * HD + d] =
                    make_float2(acc[mt][nt][0], acc[mt][nt][1]);
                *(float2*)&Cf[(size_t)((hh * S_LEN) + row + 8) * HD + d] =
                    make_float2(acc[mt][nt][2], acc[mt][nt][3]);
            }
        }
    }
#undef LDG_TILE
#undef STS_TILE
#undef COMPUTE
}

// ---------------- RoPE (writes bf16 hi/lo directly) -------------------------
__global__ void rope_q_kernel()
{
    int idx = blockIdx.x * blockDim.x + threadIdx.x;
    if (idx >= S_LEN * NH * 32) return;
    int i = idx & 31;
    int h = (idx >> 5) & 15;
    int t = idx >> 9;
    float invf = powf(10000.0f, -(2.0f * i) / 64.0f);
    float ang = (float)t * invf;
    float s, c;
    sincosf(ang, &s, &c);
    const float* x = g_qR + (size_t)t * (NH * DR) + h * DR;
    float x1 = x[i], x2 = x[i + 32];
    float r1 = x1 * c - x2 * s;
    float r2 = x2 * c + x1 * s;
    size_t base = ((size_t)(h * S_LEN + t)) * DQK + HD;
    unsigned short hh, ll;
    split2(r1, hh, ll); g_QH[base + i] = hh;      g_QL[base + i] = ll;
    split2(r2, hh, ll); g_QH[base + i + 32] = hh; g_QL[base + i + 32] = ll;
}

__global__ void rope_k_kernel()
{
    int idx = blockIdx.x * blockDim.x + threadIdx.x;
    if (idx >= S_LEN * 32) return;
    int i = idx & 31;
    int t = idx >> 5;
    float invf = powf(10000.0f, -(2.0f * i) / 64.0f);
    float ang = (float)t * invf;
    float s, c;
    sincosf(ang, &s, &c);
    const float* x = g_kR + (size_t)t * DR;
    float r1 = x[i] * c - x[i + 32] * s;
    float r2 = x[i + 32] * c + x[i] * s;
    unsigned short h1, l1, h2, l2;
    split2(r1, h1, l1);
    split2(r2, h2, l2);
#pragma unroll
    for (int h = 0; h < NH; h++) {
        size_t base = ((size_t)(h * S_LEN + t)) * DQK + HD;
        g_KH[base + i] = h1;      g_KL[base + i] = l1;
        g_KH[base + i + 32] = h2; g_KL[base + i + 32] = l2;
    }
}

// ---------------- V transpose + bf16 split prepass ---------------------------
// g_Vb [h][s][128] f32 -> g_VTH/g_VTL [h][d][s] bf16
__global__ __launch_bounds__(256)
void vtrans_kernel()
{
    __shared__ float sv[64][133];
    const int h  = blockIdx.y;
    const int s0 = blockIdx.x * 64;
    const int tid = threadIdx.x;
    const float* src = g_Vb + ((size_t)h * S_LEN + s0) * HD;
#pragma unroll
    for (int i = 0; i < 8; i++) {
        int idx = tid + i * 256;
        int r = idx >> 5, c4 = (idx & 31) * 4;
        float4 v = *(const float4*)&src[r * HD + c4];
        sv[r][c4] = v.x; sv[r][c4 + 1] = v.y; sv[r][c4 + 2] = v.z; sv[r][c4 + 3] = v.w;
    }
    __syncthreads();
    int s = tid & 63, d0 = tid >> 6;
#pragma unroll
    for (int dd = 0; dd < 32; dd++) {
        int d = d0 * 32 + dd;
        unsigned short hh, ll;
        split2(sv[s][d], hh, ll);
        size_t o = ((size_t)(h * HD + d)) * S_LEN + s0 + s;
        g_VTH[o] = hh;
        g_VTL[o] = ll;
    }
}

// ---------------- bf16x3 tensor-core flash attention -------------------------
// smem: QH[128][200] @0, QL @51200, KH[64][200] @102400, KL @128000,
//       VTH[128][72] @153600, VTL @172032, red[256] @190464
#define ATTN_SMEM 191488

__global__ __launch_bounds__(256, 1)
void attn_mma_kernel()
{
    extern __shared__ char smraw[];
    unsigned short* QH  = (unsigned short*)(smraw);
    unsigned short* QL  = (unsigned short*)(smraw + 51200);
    unsigned short* KH  = (unsigned short*)(smraw + 102400);
    unsigned short* KL  = (unsigned short*)(smraw + 128000);
    unsigned short* VTH = (unsigned short*)(smraw + 153600);
    unsigned short* VTL = (unsigned short*)(smraw + 172032);
    float* red = (float*)(smraw + 190464);

    const int bid  = blockIdx.x;
    const int mb   = 15 - (bid >> 4);
    const int h    = bid & 15;
    const int m0   = mb * 128;
    const int tid  = threadIdx.x;
    const int lane = tid & 31;
    const int warp = tid >> 5;
    const int wm = warp >> 1, wn = warp & 1;
    const int g = lane >> 2, t = lane & 3;

    // stage Q (pure copy, bf16 pre-split)
    {
        const uint4* sH = (const uint4*)(g_QH + ((size_t)h * S_LEN + m0) * DQK);
        const uint4* sL = (const uint4*)(g_QL + ((size_t)h * S_LEN + m0) * DQK);
        uint4* dH = (uint4*)QH;
        uint4* dL = (uint4*)QL;
#pragma unroll
        for (int i = 0; i < 12; i++) {
            int idx = tid + i * 256;
            int r = idx / 24, u = idx - r * 24;
            dH[r * 25 + u] = sH[idx];
            dL[r * 25 + u] = sL[idx];
        }
    }

    float oacc[2][16][4];
#pragma unroll
    for (int mt = 0; mt < 2; mt++)
#pragma unroll
        for (int nt = 0; nt < 16; nt++)
#pragma unroll
            for (int c = 0; c < 4; c++) oacc[mt][nt][c] = 0.f;

    float mrow[2][2] = {{-1e30f, -1e30f}, {-1e30f, -1e30f}};
    float lrow[2][2] = {{0.f, 0.f}, {0.f, 0.f}};   // per-thread, pair-local

    const float scale = 0.07216878364870322f;
    const int ntiles = 2 * mb + 2;

    const uint4* KHg = (const uint4*)(g_KH + (size_t)h * S_LEN * DQK);
    const uint4* KLg = (const uint4*)(g_KL + (size_t)h * S_LEN * DQK);
    const uint4* VHg = (const uint4*)(g_VTH + (size_t)h * HD * S_LEN);
    const uint4* VLg = (const uint4*)(g_VTL + (size_t)h * HD * S_LEN);
    uint4* KH4 = (uint4*)KH;
    uint4* KL4 = (uint4*)KL;
    uint4* VH4 = (uint4*)VTH;
    uint4* VL4 = (uint4*)VTL;

#pragma unroll 1
    for (int tile = 0; tile < ntiles; tile++) {
        const int n0 = tile * 64;
        __syncthreads();

        // stage K tile: 64 rows x 24 uint4 (contiguous gmem, stride-25 smem)
        {
            const uint4* sH = KHg + (size_t)n0 * 24;
            const uint4* sL = KLg + (size_t)n0 * 24;
#pragma unroll
            for (int i = 0; i < 6; i++) {
                int idx = tid + i * 256;
                int r = idx / 24, u = idx - r * 24;
                KH4[r * 25 + u] = sH[idx];
                KL4[r * 25 + u] = sL[idx];
            }
        }
        // stage V tile: 128 d-rows x 8 uint4 (gmem row stride 256 uint4)
        {
            const uint4* sH = VHg + (n0 >> 3);
            const uint4* sL = VLg + (n0 >> 3);
#pragma unroll
            for (int i = 0; i < 4; i++) {
                int idx = tid + i * 256;
                int d = idx >> 3, u = idx & 7;
                VH4[d * 9 + u] = sH[d * 256 + u];
                VL4[d * 9 + u] = sL[d * 256 + u];
            }
        }
        __syncthreads();

        // ---- S = Q K^T (bf16x3) ----
        float sacc[2][4][4];
#pragma unroll
        for (int mt = 0; mt < 2; mt++)
#pragma unroll
            for (int nt = 0; nt < 4; nt++)
#pragma unroll
                for (int c = 0; c < 4; c++) sacc[mt][nt][c] = 0.f;

#pragma unroll
        for (int kt = 0; kt < 12; kt++) {
            unsigned ah[2][4], al[2][4];
#pragma unroll
            for (int mt = 0; mt < 2; mt++) {
                int rb = (wm * 32 + mt * 16 + g) * 200 + kt * 16 + 2 * t;
                ah[mt][0] = *(const unsigned*)&QH[rb];
                ah[mt][1] = *(const unsigned*)&QH[rb + 1600];
                ah[mt][2] = *(const unsigned*)&QH[rb + 8];
                ah[mt][3] = *(const unsigned*)&QH[rb + 1608];
                al[mt][0] = *(const unsigned*)&QL[rb];
                al[mt][1] = *(const unsigned*)&QL[rb + 1600];
                al[mt][2] = *(const unsigned*)&QL[rb + 8];
                al[mt][3] = *(const unsigned*)&QL[rb + 1608];
            }
#pragma unroll
            for (int nt = 0; nt < 4; nt++) {
                int nb = (wn * 32 + nt * 8 + g) * 200 + kt * 16 + 2 * t;
                unsigned bh[2] = {*(const unsigned*)&KH[nb], *(const unsigned*)&KH[nb + 8]};
                unsigned bl[2] = {*(const unsigned*)&KL[nb], *(const unsigned*)&KL[nb + 8]};
#pragma unroll
                for (int mt = 0; mt < 2; mt++) {
                    mma16(sacc[mt][nt], ah[mt], bh);
                    mma16(sacc[mt][nt], ah[mt], bl);
                    mma16(sacc[mt][nt], al[mt], bh);
                }
            }
        }

        // ---- scale + causal mask ----
#pragma unroll
        for (int mt = 0; mt < 2; mt++)
#pragma unroll
            for (int nt = 0; nt < 4; nt++)
#pragma unroll
                for (int c = 0; c < 4; c++) {
                    int col = n0 + wn * 32 + nt * 8 + 2 * t + (c & 1);
                    int row = m0 + wm * 32 + mt * 16 + g + (c >> 1) * 8;
                    float v = sacc[mt][nt][c] * scale;
                    if (col > row) v = -1e30f;
                    sacc[mt][nt][c] = v;
                }

        // ---- online softmax (ONE cross-pair sync; l kept pair-local) ----
        float pmv[2][2], alpha_[2][2];
#pragma unroll
        for (int mt = 0; mt < 2; mt++)
#pragma unroll
            for (int hf = 0; hf < 2; hf++) {
                float pm = -1e30f;
#pragma unroll
                for (int nt = 0; nt < 4; nt++)
                    pm = fmaxf(pm, fmaxf(sacc[mt][nt][hf * 2], sacc[mt][nt][hf * 2 + 1]));
                pm = fmaxf(pm, __shfl_xor_sync(0xffffffffu, pm, 1));
                pm = fmaxf(pm, __shfl_xor_sync(0xffffffffu, pm, 2));
                pmv[mt][hf] = pm;
                if (t == 0) red[wn * 128 + wm * 32 + mt * 16 + hf * 8 + g] = pm;
            }
        __syncthreads();
#pragma unroll
        for (int mt = 0; mt < 2; mt++)
#pragma unroll
            for (int hf = 0; hf < 2; hf++) {
                int rowl = wm * 32 + mt * 16 + hf * 8 + g;
                float comb = fmaxf(pmv[mt][hf], red[(wn ^ 1) * 128 + rowl]);
                float mnew = fmaxf(mrow[mt][hf], comb);
                alpha_[mt][hf] = __expf(mrow[mt][hf] - mnew);
                mrow[mt][hf] = mnew;
                float ps = 0.f;
#pragma unroll
                for (int nt = 0; nt < 4; nt++)
#pragma unroll
                    for (int k2 = 0; k2 < 2; k2++) {
                        int c = hf * 2 + k2;
                        float p = __expf(sacc[mt][nt][c] - mnew);
                        sacc[mt][nt][c] = p;
                        ps += p;
                    }
                lrow[mt][hf] = lrow[mt][hf] * alpha_[mt][hf] + ps;  // own cols only
            }
#pragma unroll
        for (int mt = 0; mt < 2; mt++)
#pragma unroll
            for (int nt = 0; nt < 16; nt++)
#pragma unroll
                for (int c = 0; c < 4; c++)
                    oacc[mt][nt][c] *= alpha_[mt][c >> 1];

        // ---- O += P V (bf16x3) ----
#pragma unroll
        for (int kt2 = 0; kt2 < 2; kt2++) {
            unsigned aph[2][4], apl[2][4];
#pragma unroll
            for (int mt = 0; mt < 2; mt++) {
                aph[mt][0] = packsplit(sacc[mt][2 * kt2][0],     sacc[mt][2 * kt2][1],     apl[mt][0]);
                aph[mt][1] = packsplit(sacc[mt][2 * kt2][2],     sacc[mt][2 * kt2][3],     apl[mt][1]);
                aph[mt][2] = packsplit(sacc[mt][2 * kt2 + 1][0], sacc[mt][2 * kt2 + 1][1], apl[mt][2]);
                aph[mt][3] = packsplit(sacc[mt][2 * kt2 + 1][2], sacc[mt][2 * kt2 + 1][3], apl[mt][3]);
            }
#pragma unroll
            for (int nt = 0; nt < 16; nt++) {
                int vb = (nt * 8 + g) * 72 + wn * 32 + kt2 * 16 + 2 * t;
                unsigned bh[2] = {*(const unsigned*)&VTH[vb], *(const unsigned*)&VTH[vb + 8]};
                unsigned bl[2] = {*(const unsigned*)&VTL[vb], *(const unsigned*)&VTL[vb + 8]};
#pragma unroll
                for (int mt = 0; mt < 2; mt++) {
                    mma16(oacc[mt][nt], aph[mt], bh);
                    mma16(oacc[mt][nt], aph[mt], bl);
                    mma16(oacc[mt][nt], apl[mt], bh);
                }
            }
        }
    }

    // ---- epilogue: reduce l over quad, exchange O + l across wn pair ----
    float lsum[2][2];
#pragma unroll
    for (int mt = 0; mt < 2; mt++)
#pragma unroll
        for (int hf = 0; hf < 2; hf++) {
            float lq = lrow[mt][hf];
            lq += __shfl_xor_sync(0xffffffffu, lq, 1);
            lq += __shfl_xor_sync(0xffffffffu, lq, 2);
            lsum[mt][hf] = lq;
        }

    __syncthreads();
    float* osm = (float*)smraw + wm * (32 * 132);   // Q area is dead now
    if (wn == 1) {
#pragma unroll
        for (int mt = 0; mt < 2; mt++)
#pragma unroll
            for (int nt = 0; nt < 16; nt++)
#pragma unroll
                for (int c = 0; c < 4; c++) {
                    int rowl = mt * 16 + (c >> 1) * 8 + g;
                    int col = nt * 8 + 2 * t + (c & 1);
                    osm[rowl * 132 + col] = oacc[mt][nt][c];
                }
#pragma unroll
        for (int mt = 0; mt < 2; mt++)
#pragma unroll
            for (int hf = 0; hf < 2; hf++)
                if (t == 0) red[wm * 32 + mt * 16 + hf * 8 + g] = lsum[mt][hf];
    }
    __syncthreads();
    if (wn == 0) {
#pragma unroll
        for (int mt = 0; mt < 2; mt++)
#pragma unroll
            for (int hf = 0; hf < 2; hf++) {
                int rowl = mt * 16 + hf * 8 + g;
                float ltot = lsum[mt][hf] + red[wm * 32 + rowl];
                float inv = 1.f / ltot;
                int row = m0 + wm * 32 + rowl;
#pragma unroll
                for (int nt = 0; nt < 16; nt++) {
                    int col = nt * 8 + 2 * t;
                    float v0 = (oacc[mt][nt][hf * 2]     + osm[rowl * 132 + col])     * inv;
                    float v1 = (oacc[mt][nt][hf * 2 + 1] + osm[rowl * 132 + col + 1]) * inv;
                    *(float2*)&g_AO[(size_t)row * (NH * HD) + h * HD + col] = make_float2(v0, v1);
                }
            }
    }
}

// ---------------- launch ----------------------------------------------------
extern "C" void kernel_launch(void* const* d_in, const int* in_sizes, int n_in,
                              void* d_out, int out_size)
{
    const float* X     = (const float*)d_in[0];
    const float* W_DKV = (const float*)d_in[2];
    const float* W_UK  = (const float*)d_in[3];
    const float* W_UV  = (const float*)d_in[4];
    const float* W_DQ  = (const float*)d_in[5];
    const float* W_UQ  = (const float*)d_in[6];
    const float* W_QR  = (const float*)d_in[7];
    const float* W_KR  = (const float*)d_in[8];
    const float* W_O   = (const float*)d_in[9];
    float* out = (float*)d_out;

    float *cKV, *cQ, *qR, *kR, *Vb, *AO;
    unsigned short *QHp, *QLp, *KHp, *KLp;
    cudaGetSymbolAddress((void**)&cKV, g_cKV);
    cudaGetSymbolAddress((void**)&cQ,  g_cQ);
    cudaGetSymbolAddress((void**)&qR,  g_qR);
    cudaGetSymbolAddress((void**)&kR,  g_kR);
    cudaGetSymbolAddress((void**)&Vb,  g_Vb);
    cudaGetSymbolAddress((void**)&AO,  g_AO);
    cudaGetSymbolAddress((void**)&QHp, g_QH);
    cudaGetSymbolAddress((void**)&QLp, g_QL);
    cudaGetSymbolAddress((void**)&KHp, g_KH);
    cudaGetSymbolAddress((void**)&KLp, g_KL);

    dim3 blk(256);

    // P1: X @ {W_DQ, W_DKV, W_KR}
    {
        GroupArgs ga = {};
        ga.A[0] = X;  ga.B[0] = W_DQ;  ga.C[0] = cQ;  ga.K[0] = HID_D; ga.N[0] = CQ;   ga.mode[0] = 0;
        ga.A[1] = X;  ga.B[1] = W_DKV; ga.C[1] = cKV; ga.K[1] = HID_D; ga.N[1] = CKV;  ga.mode[1] = 0;
        ga.A[2] = X;  ga.B[2] = W_KR;  ga.C[2] = kR;  ga.K[2] = HID_D; ga.N[2] = DR;   ga.mode[2] = 0;
        ga.tstart[0] = 0; ga.tstart[1] = 12; ga.tstart[2] = 16; ga.tstart[3] = 17; ga.tstart[4] = 17;
        mma_gemm_grouped<<<dim3(16, 17), blk>>>(ga);
    }
    // P2: {UQ->bf16 Q, QR->qR, UK->bf16 K, UV->V f32}; long-K groups first
    {
        GroupArgs ga = {};
        ga.A[0] = cQ;  ga.B[0] = W_UQ; ga.C[0] = QHp; ga.Clo[0] = QLp; ga.K[0] = CQ;  ga.N[0] = NH * HD; ga.mode[0] = 1;
        ga.A[1] = cQ;  ga.B[1] = W_QR; ga.C[1] = qR;                   ga.K[1] = CQ;  ga.N[1] = NH * DR; ga.mode[1] = 0;
        ga.A[2] = cKV; ga.B[2] = W_UK; ga.C[2] = KHp; ga.Clo[2] = KLp; ga.K[2] = CKV; ga.N[2] = NH * HD; ga.mode[2] = 1;
        ga.A[3] = cKV; ga.B[3] = W_UV; ga.C[3] = Vb;                   ga.K[3] = CKV; ga.N[3] = NH * HD; ga.mode[3] = 2;
        ga.tstart[0] = 0; ga.tstart[1] = 16; ga.tstart[2] = 24; ga.tstart[3] = 40; ga.tstart[4] = 56;
        mma_gemm_grouped<<<dim3(16, 56), blk>>>(ga);
    }

    rope_q_kernel<<<(S_LEN * NH * 32) / 256, 256>>>();
    rope_k_kernel<<<(S_LEN * 32) / 256, 256>>>();
    vtrans_kernel<<<dim3(S_LEN / 64, NH), 256>>>();

    cudaFuncSetAttribute(attn_mma_kernel, cudaFuncAttributeMaxDynamicSharedMemorySize, ATTN_SMEM);
    attn_mma_kernel<<<256, 256, ATTN_SMEM>>>();

    // out = AO @ W_O
    {
        GroupArgs ga = {};
        ga.A[0] = AO; ga.B[0] = W_O; ga.C[0] = out; ga.K[0] = NH * HD; ga.N[0] = HID_D; ga.mode[0] = 0;
        ga.tstart[0] = 0; ga.tstart[1] = 16; ga.tstart[2] = 16; ga.tstart[3] = 16; ga.tstart[4] = 16;
        mma_gemm_grouped<<<dim3(16, 16), blk>>>(ga);
    }
}